// round 6
// baseline (speedup 1.0000x reference)
#include <cuda_runtime.h>
#include <math.h>
#include <stdint.h>

#define BB 4
#define NTOK 2048
#define DMODEL 1024
#define NH 16
#define DH 64
#define MROWS (BB * NTOK)            // 8192
#define QKVCOLS (3 * DMODEL)         // 3072

// Scratch (no allocations allowed)
__device__ float g_qkv[(size_t)MROWS * QKVCOLS];   // 96 MB
__device__ float g_att[(size_t)MROWS * DMODEL];    // 32 MB

__device__ __forceinline__ uint32_t f2tf32(float x) {
    uint32_t u;
    asm volatile("cvt.rna.tf32.f32 %0, %1;" : "=r"(u) : "f"(x));
    return u;
}

// ---------------------------------------------------------------------------
// TF32 tensor-core GEMM, high arithmetic-intensity version.
// C[M,N] = A[M,K] @ B[K,N] + bias[N]
// CTA tile 128x256, BK=16, 256 threads = 8 warps (2x4), warp tile 64x64.
// Fragment traffic: 0.0625 B/flop (was 0.094) -> tensor-bound mainloop.
// Smem double-buffered, one __syncthreads per K-iter, register prefetch.
// ---------------------------------------------------------------------------
#define GBK 16
#define GAPAD 20            // 16 + 4 : A frag LDS conflict-free (banks 20*gr+gc)
#define GBPAD 260           // 256 + 4
#define GASTRIDE (128 * GAPAD)
#define GBSTRIDE (GBK * GBPAD)

__global__ __launch_bounds__(256, 1) void gemm_tf32_bias(
    const float* __restrict__ A,
    const float* __restrict__ B,
    const float* __restrict__ bias,
    float* __restrict__ C,
    int M, int N, int K)
{
    extern __shared__ uint32_t smem_g[];
    uint32_t* As = smem_g;                    // 2 stages of 128*GAPAD
    uint32_t* Bs = smem_g + 2 * GASTRIDE;     // 2 stages of GBK*GBPAD

    const int tid  = threadIdx.x;
    const int lane = tid & 31;
    const int wid  = tid >> 5;
    const int row0 = blockIdx.y * 128;
    const int col0 = blockIdx.x * 256;

    // warp layout: 2 (m) x 4 (n); warp tile 64x64
    const int wm0 = (wid >> 2) * 64;
    const int wn0 = (wid & 3) * 64;
    const int gr  = lane >> 2;
    const int gc  = lane & 3;

    // producer mappings
    const int arow = tid >> 1;                // 0..127
    const int acol = (tid & 1) * 8;           // 0 or 8
    const int brow = tid >> 4;                // 0..15
    const int bcol = (tid & 15) * 16;         // 0..240

    float4 aReg[2], bReg[4];
    const int niter = K / GBK;                // 64

    // prefetch tile 0 and stage into buffer 0
    {
        const float* ap = &A[(size_t)(row0 + arow) * K + acol];
        aReg[0] = *(const float4*)(ap);
        aReg[1] = *(const float4*)(ap + 4);
        const float* bp = &B[(size_t)brow * N + col0 + bcol];
        #pragma unroll
        for (int p = 0; p < 4; p++) bReg[p] = *(const float4*)(bp + p * 4);
    }
    {
        uint32_t* as = &As[arow * GAPAD + acol];
        as[0] = f2tf32(aReg[0].x); as[1] = f2tf32(aReg[0].y);
        as[2] = f2tf32(aReg[0].z); as[3] = f2tf32(aReg[0].w);
        as[4] = f2tf32(aReg[1].x); as[5] = f2tf32(aReg[1].y);
        as[6] = f2tf32(aReg[1].z); as[7] = f2tf32(aReg[1].w);
        uint32_t* bs = &Bs[brow * GBPAD + bcol];
        #pragma unroll
        for (int p = 0; p < 4; p++) {
            bs[4 * p + 0] = f2tf32(bReg[p].x); bs[4 * p + 1] = f2tf32(bReg[p].y);
            bs[4 * p + 2] = f2tf32(bReg[p].z); bs[4 * p + 3] = f2tf32(bReg[p].w);
        }
    }

    float acc[4][8][4];
    #pragma unroll
    for (int i = 0; i < 4; i++)
        #pragma unroll
        for (int j = 0; j < 8; j++)
            #pragma unroll
            for (int q = 0; q < 4; q++) acc[i][j][q] = 0.f;

    for (int it = 0; it < niter; it++) {
        __syncthreads();
        const uint32_t* Ab = As + (it & 1) * GASTRIDE;
        const uint32_t* Bb = Bs + (it & 1) * GBSTRIDE;

        // prefetch next tile (overlaps compute)
        if (it + 1 < niter) {
            const int k0 = (it + 1) * GBK;
            const float* ap = &A[(size_t)(row0 + arow) * K + k0 + acol];
            aReg[0] = *(const float4*)(ap);
            aReg[1] = *(const float4*)(ap + 4);
            const float* bp = &B[(size_t)(k0 + brow) * N + col0 + bcol];
            #pragma unroll
            for (int p = 0; p < 4; p++) bReg[p] = *(const float4*)(bp + p * 4);
        }

        // compute: 2 ksteps of 8
        #pragma unroll
        for (int kk = 0; kk < 2; kk++) {
            const int kb = kk * 8;
            uint32_t af[4][4], bf[8][2];
            #pragma unroll
            for (int mt = 0; mt < 4; mt++) {
                const uint32_t* base = &Ab[(wm0 + mt * 16 + gr) * GAPAD + kb + gc];
                af[mt][0] = base[0];
                af[mt][1] = base[8 * GAPAD];
                af[mt][2] = base[4];
                af[mt][3] = base[8 * GAPAD + 4];
            }
            #pragma unroll
            for (int nt = 0; nt < 8; nt++) {
                const uint32_t* base = &Bb[(kb + gc) * GBPAD + wn0 + nt * 8 + gr];
                bf[nt][0] = base[0];
                bf[nt][1] = base[4 * GBPAD];
            }
            #pragma unroll
            for (int mt = 0; mt < 4; mt++)
                #pragma unroll
                for (int nt = 0; nt < 8; nt++) {
                    asm volatile(
                        "mma.sync.aligned.m16n8k8.row.col.f32.tf32.tf32.f32 "
                        "{%0,%1,%2,%3}, {%4,%5,%6,%7}, {%8,%9}, {%0,%1,%2,%3};"
                        : "+f"(acc[mt][nt][0]), "+f"(acc[mt][nt][1]),
                          "+f"(acc[mt][nt][2]), "+f"(acc[mt][nt][3])
                        : "r"(af[mt][0]), "r"(af[mt][1]), "r"(af[mt][2]), "r"(af[mt][3]),
                          "r"(bf[nt][0]), "r"(bf[nt][1]));
                }
        }

        // stage next tile into other buffer
        if (it + 1 < niter) {
            uint32_t* Aw = As + ((it + 1) & 1) * GASTRIDE;
            uint32_t* Bw = Bs + ((it + 1) & 1) * GBSTRIDE;
            uint32_t* as = &Aw[arow * GAPAD + acol];
            as[0] = f2tf32(aReg[0].x); as[1] = f2tf32(aReg[0].y);
            as[2] = f2tf32(aReg[0].z); as[3] = f2tf32(aReg[0].w);
            as[4] = f2tf32(aReg[1].x); as[5] = f2tf32(aReg[1].y);
            as[6] = f2tf32(aReg[1].z); as[7] = f2tf32(aReg[1].w);
            uint32_t* bs = &Bw[brow * GBPAD + bcol];
            #pragma unroll
            for (int p = 0; p < 4; p++) {
                bs[4 * p + 0] = f2tf32(bReg[p].x); bs[4 * p + 1] = f2tf32(bReg[p].y);
                bs[4 * p + 2] = f2tf32(bReg[p].z); bs[4 * p + 3] = f2tf32(bReg[p].w);
            }
        }
    }

    // epilogue: add bias, store (float2 per fragment row-pair)
    #pragma unroll
    for (int mt = 0; mt < 4; mt++) {
        int r = row0 + wm0 + mt * 16 + gr;
        #pragma unroll
        for (int nt = 0; nt < 8; nt++) {
            int c = col0 + wn0 + nt * 8 + 2 * gc;
            float bv0 = bias[c], bv1 = bias[c + 1];
            *(float2*)&C[(size_t)r * N + c] =
                make_float2(acc[mt][nt][0] + bv0, acc[mt][nt][1] + bv1);
            *(float2*)&C[(size_t)(r + 8) * N + c] =
                make_float2(acc[mt][nt][2] + bv0, acc[mt][nt][3] + bv1);
        }
    }
}

// ---------------------------------------------------------------------------
// TF32 tensor-core causal flash attention (exact R3 version — known good).
// ---------------------------------------------------------------------------
#define QT 128
#define KT 64
#define QPAD 68

__global__ __launch_bounds__(256, 2) void attn_tf32(
    const float* __restrict__ qkv, float* __restrict__ out)
{
    extern __shared__ uint32_t sm_u[];
    uint32_t* Qs = sm_u;
    uint32_t* Ks = Qs + QT * QPAD;
    uint32_t* Vs = Ks + KT * QPAD;
    uint32_t* Ps = Vs + KT * QPAD;

    const int tid  = threadIdx.x;
    const int lane = tid & 31;
    const int wid  = tid >> 5;
    const int gr   = lane >> 2;
    const int gc   = lane & 3;

    const int bh = blockIdx.x;
    const int b  = bh >> 4;
    const int h  = bh & 15;
    const int qi = (gridDim.y - 1) - blockIdx.y;
    const int q0 = qi * QT;
    const float scale = 0.125f;

    {
        const size_t qbase = (size_t)(b * NTOK + q0) * QKVCOLS + h * DH;
        #pragma unroll
        for (int p = 0; p < 8; p++) {
            int idx = tid + p * 256;
            int r = idx >> 4, c = (idx & 15) * 4;
            float4 v = *(const float4*)&qkv[qbase + (size_t)r * QKVCOLS + c];
            uint32_t* d = &Qs[r * QPAD + c];
            d[0] = f2tf32(v.x); d[1] = f2tf32(v.y);
            d[2] = f2tf32(v.z); d[3] = f2tf32(v.w);
        }
    }

    float accO[8][4];
    #pragma unroll
    for (int nt = 0; nt < 8; nt++)
        #pragma unroll
        for (int q = 0; q < 4; q++) accO[nt][q] = 0.f;
    float mrow[2] = { -INFINITY, -INFINITY };
    float lrow[2] = { 0.f, 0.f };

    const size_t kvbase = (size_t)(b * NTOK) * QKVCOLS + DMODEL + h * DH;
    const int nkv = 2 * qi + 2;
    const int wrow0 = q0 + wid * 16;

    for (int j = 0; j < nkv; j++) {
        __syncthreads();
        {
            #pragma unroll
            for (int p = 0; p < 4; p++) {
                int idx = tid + p * 256;
                int r = idx >> 4, c = (idx & 15) * 4;
                size_t off = kvbase + (size_t)(j * KT + r) * QKVCOLS + c;
                float4 kv4 = *(const float4*)&qkv[off];
                float4 vv4 = *(const float4*)&qkv[off + DMODEL];
                uint32_t* dk = &Ks[r * QPAD + c];
                dk[0] = f2tf32(kv4.x); dk[1] = f2tf32(kv4.y);
                dk[2] = f2tf32(kv4.z); dk[3] = f2tf32(kv4.w);
                uint32_t* dv = &Vs[r * QPAD + c];
                dv[0] = f2tf32(vv4.x); dv[1] = f2tf32(vv4.y);
                dv[2] = f2tf32(vv4.z); dv[3] = f2tf32(vv4.w);
            }
        }
        __syncthreads();

        if (j * KT > wrow0 + 15) continue;

        float s[8][4];
        #pragma unroll
        for (int nt = 0; nt < 8; nt++)
            #pragma unroll
            for (int q = 0; q < 4; q++) s[nt][q] = 0.f;

        #pragma unroll
        for (int kb = 0; kb < 8; kb++) {
            const uint32_t* abase = &Qs[(wid * 16 + gr) * QPAD + kb * 8 + gc];
            uint32_t a0 = abase[0], a1 = abase[8 * QPAD];
            uint32_t a2 = abase[4], a3 = abase[8 * QPAD + 4];
            #pragma unroll
            for (int nt = 0; nt < 8; nt++) {
                const uint32_t* bbase = &Ks[(nt * 8 + gr) * QPAD + kb * 8 + gc];
                uint32_t b0 = bbase[0], b1 = bbase[4];
                asm volatile(
                    "mma.sync.aligned.m16n8k8.row.col.f32.tf32.tf32.f32 "
                    "{%0,%1,%2,%3}, {%4,%5,%6,%7}, {%8,%9}, {%0,%1,%2,%3};"
                    : "+f"(s[nt][0]), "+f"(s[nt][1]), "+f"(s[nt][2]), "+f"(s[nt][3])
                    : "r"(a0), "r"(a1), "r"(a2), "r"(a3), "r"(b0), "r"(b1));
            }
        }

        if (j * KT + KT - 1 <= wrow0) {
            #pragma unroll
            for (int nt = 0; nt < 8; nt++)
                #pragma unroll
                for (int q = 0; q < 4; q++) s[nt][q] *= scale;
        } else {
            const int r0g = wrow0 + gr, r1g = wrow0 + gr + 8;
            #pragma unroll
            for (int nt = 0; nt < 8; nt++) {
                int c0g = j * KT + nt * 8 + 2 * gc;
                s[nt][0] = (c0g     <= r0g) ? s[nt][0] * scale : -INFINITY;
                s[nt][1] = (c0g + 1 <= r0g) ? s[nt][1] * scale : -INFINITY;
                s[nt][2] = (c0g     <= r1g) ? s[nt][2] * scale : -INFINITY;
                s[nt][3] = (c0g + 1 <= r1g) ? s[nt][3] * scale : -INFINITY;
            }
        }

        #pragma unroll
        for (int half = 0; half < 2; half++) {
            float tmax = -INFINITY;
            #pragma unroll
            for (int nt = 0; nt < 8; nt++)
                tmax = fmaxf(tmax, fmaxf(s[nt][2 * half], s[nt][2 * half + 1]));
            tmax = fmaxf(tmax, __shfl_xor_sync(0xffffffffu, tmax, 1));
            tmax = fmaxf(tmax, __shfl_xor_sync(0xffffffffu, tmax, 2));
            float mnew  = fmaxf(mrow[half], tmax);
            float alpha = __expf(mrow[half] - mnew);
            float sum = 0.f;
            const int prow = (wid * 16 + gr + 8 * half) * QPAD;
            #pragma unroll
            for (int nt = 0; nt < 8; nt++) {
                float p0 = __expf(s[nt][2 * half]     - mnew);
                float p1 = __expf(s[nt][2 * half + 1] - mnew);
                sum += p0 + p1;
                Ps[prow + nt * 8 + 2 * gc]     = f2tf32(p0);
                Ps[prow + nt * 8 + 2 * gc + 1] = f2tf32(p1);
            }
            sum += __shfl_xor_sync(0xffffffffu, sum, 1);
            sum += __shfl_xor_sync(0xffffffffu, sum, 2);
            lrow[half] = lrow[half] * alpha + sum;
            mrow[half] = mnew;
            #pragma unroll
            for (int nt = 0; nt < 8; nt++) {
                accO[nt][2 * half]     *= alpha;
                accO[nt][2 * half + 1] *= alpha;
            }
        }
        __syncwarp();

        #pragma unroll
        for (int kb = 0; kb < 8; kb++) {
            const uint32_t* abase = &Ps[(wid * 16 + gr) * QPAD + kb * 8 + gc];
            uint32_t a0 = abase[0], a1 = abase[8 * QPAD];
            uint32_t a2 = abase[4], a3 = abase[8 * QPAD + 4];
            #pragma unroll
            for (int nt = 0; nt < 8; nt++) {
                uint32_t b0 = Vs[(kb * 8 + gc) * QPAD + nt * 8 + gr];
                uint32_t b1 = Vs[(kb * 8 + gc + 4) * QPAD + nt * 8 + gr];
                asm volatile(
                    "mma.sync.aligned.m16n8k8.row.col.f32.tf32.tf32.f32 "
                    "{%0,%1,%2,%3}, {%4,%5,%6,%7}, {%8,%9}, {%0,%1,%2,%3};"
                    : "+f"(accO[nt][0]), "+f"(accO[nt][1]),
                      "+f"(accO[nt][2]), "+f"(accO[nt][3])
                    : "r"(a0), "r"(a1), "r"(a2), "r"(a3), "r"(b0), "r"(b1));
            }
        }
    }

    float inv0 = 1.f / lrow[0];
    float inv1 = 1.f / lrow[1];
    size_t r0 = (size_t)(b * NTOK + wrow0 + gr) * DMODEL + h * DH;
    size_t r1 = r0 + 8 * DMODEL;
    #pragma unroll
    for (int nt = 0; nt < 8; nt++) {
        int c = nt * 8 + 2 * gc;
        *(float2*)&out[r0 + c] = make_float2(accO[nt][0] * inv0, accO[nt][1] * inv0);
        *(float2*)&out[r1 + c] = make_float2(accO[nt][2] * inv1, accO[nt][3] * inv1);
    }
}

// ---------------------------------------------------------------------------
extern "C" void kernel_launch(void* const* d_in, const int* in_sizes, int n_in,
                              void* d_out, int out_size)
{
    const float* x     = (const float*)d_in[0];
    const float* w_qkv = (const float*)d_in[1];
    const float* b_qkv = (const float*)d_in[2];
    const float* w_out = (const float*)d_in[3];
    const float* b_out = (const float*)d_in[4];
    float* out = (float*)d_out;

    float* qkv;  cudaGetSymbolAddress((void**)&qkv, g_qkv);
    float* att;  cudaGetSymbolAddress((void**)&att, g_att);

    const int gemm_smem = (2 * GASTRIDE + 2 * GBSTRIDE) * 4;   // 53760 B
    cudaFuncSetAttribute(gemm_tf32_bias,
                         cudaFuncAttributeMaxDynamicSharedMemorySize, gemm_smem);

    // 1) QKV projection (tf32, 64x64 warp tiles)
    {
        dim3 grid(QKVCOLS / 256, MROWS / 128);   // (12, 64)
        gemm_tf32_bias<<<grid, 256, gemm_smem>>>(x, w_qkv, b_qkv, qkv,
                                                 MROWS, QKVCOLS, DMODEL);
    }

    // 2) causal flash attention (tf32 mma.sync, R3-exact)
    {
        const int smem = (QT * QPAD + 2 * KT * QPAD + QT * QPAD) * 4; // 104448 B
        cudaFuncSetAttribute(attn_tf32,
                             cudaFuncAttributeMaxDynamicSharedMemorySize, smem);
        dim3 grid(BB * NH, NTOK / QT);    // (64, 16)
        attn_tf32<<<grid, 256, smem>>>(qkv, att);
    }

    // 3) output projection (tf32, 64x64 warp tiles)
    {
        dim3 grid(DMODEL / 256, MROWS / 128);    // (4, 64)
        gemm_tf32_bias<<<grid, 256, gemm_smem>>>(att, w_out, b_out, out,
                                                 MROWS, DMODEL, DMODEL);
    }
}

// round 7
// speedup vs baseline: 1.2198x; 1.2198x over previous
#include <cuda_runtime.h>
#include <math.h>
#include <stdint.h>

#define BB 4
#define NTOK 2048
#define DMODEL 1024
#define NH 16
#define DH 64
#define MROWS (BB * NTOK)            // 8192
#define QKVCOLS (3 * DMODEL)         // 3072

// Scratch (no allocations allowed)
__device__ float g_qkv[(size_t)MROWS * QKVCOLS];   // 96 MB
__device__ float g_att[(size_t)MROWS * DMODEL];    // 32 MB

__device__ __forceinline__ uint32_t f2tf32(float x) {
    uint32_t u;
    asm volatile("cvt.rna.tf32.f32 %0, %1;" : "=r"(u) : "f"(x));
    return u;
}

// ---------------------------------------------------------------------------
// TF32 tensor-core GEMM, occupancy-first version.
// C[M,N] = A[M,K] @ B[K,N] + bias[N]
// CTA tile 64x128, BK=16, 128 threads = 4 warps (1x4), warp tile 64x32.
// ~105 regs, 13.6KB smem -> 4 CTAs/SM = 4 independent sync/load domains.
// LDGs batched before the barrier; producer stores are STS.128 (conflict-free).
// A[m][k] pad->20 (frag LDS conflict-free), B[k][n] pad->132 (frag <=distinct).
// ---------------------------------------------------------------------------
#define GBK 16
#define GAPAD 20
#define GBPAD 132
#define GASZ (64 * GAPAD)          // words
#define GBSZ (GBK * GBPAD)         // words

__global__ __launch_bounds__(128, 4) void gemm_tf32_bias(
    const float* __restrict__ A,
    const float* __restrict__ B,
    const float* __restrict__ bias,
    float* __restrict__ C,
    int M, int N, int K)
{
    extern __shared__ uint32_t smem_g[];
    uint32_t* As = smem_g;             // [64][GAPAD]
    uint32_t* Bs = smem_g + GASZ;      // [GBK][GBPAD]

    const int tid  = threadIdx.x;
    const int lane = tid & 31;
    const int wid  = tid >> 5;         // 0..3
    const int row0 = blockIdx.y * 64;
    const int col0 = blockIdx.x * 128;

    const int wn0 = wid * 32;
    const int gr  = lane >> 2;
    const int gc  = lane & 3;

    // producer coords
    const int ar = tid >> 2;           // 0..31 (and +32)
    const int ac = (tid & 3) * 4;      // k-col (float4)
    const int br = tid >> 5;           // 0..3 (+4p)
    const int bc = (tid & 31) * 4;     // n-col (float4)

    float acc[4][4][4];
    #pragma unroll
    for (int i = 0; i < 4; i++)
        #pragma unroll
        for (int j = 0; j < 4; j++)
            #pragma unroll
            for (int q = 0; q < 4; q++) acc[i][j][q] = 0.f;

    const int niter = K / GBK;         // 64

    for (int it = 0; it < niter; it++) {
        const int k0 = it * GBK;

        // ---- batched global loads (issued while other warps still compute) ----
        float4 a0 = *(const float4*)&A[(size_t)(row0 + ar)      * K + k0 + ac];
        float4 a1 = *(const float4*)&A[(size_t)(row0 + ar + 32) * K + k0 + ac];
        float4 b4[4];
        #pragma unroll
        for (int p = 0; p < 4; p++)
            b4[p] = *(const float4*)&B[(size_t)(k0 + br + 4 * p) * N + col0 + bc];

        __syncthreads();   // all warps done reading previous stage

        // ---- store to smem (tf32), vectorized STS.128 ----
        {
            uint4 u;
            u.x = f2tf32(a0.x); u.y = f2tf32(a0.y); u.z = f2tf32(a0.z); u.w = f2tf32(a0.w);
            *(uint4*)&As[ar * GAPAD + ac] = u;
            u.x = f2tf32(a1.x); u.y = f2tf32(a1.y); u.z = f2tf32(a1.z); u.w = f2tf32(a1.w);
            *(uint4*)&As[(ar + 32) * GAPAD + ac] = u;
            #pragma unroll
            for (int p = 0; p < 4; p++) {
                u.x = f2tf32(b4[p].x); u.y = f2tf32(b4[p].y);
                u.z = f2tf32(b4[p].z); u.w = f2tf32(b4[p].w);
                *(uint4*)&Bs[(br + 4 * p) * GBPAD + bc] = u;
            }
        }
        __syncthreads();   // stage visible

        // ---- compute: 2 ksteps of 8 ----
        #pragma unroll
        for (int kk = 0; kk < 2; kk++) {
            const int kb = kk * 8;
            uint32_t af[4][4], bf[4][2];
            #pragma unroll
            for (int mt = 0; mt < 4; mt++) {
                const uint32_t* base = &As[(mt * 16 + gr) * GAPAD + kb + gc];
                af[mt][0] = base[0];
                af[mt][1] = base[8 * GAPAD];
                af[mt][2] = base[4];
                af[mt][3] = base[8 * GAPAD + 4];
            }
            #pragma unroll
            for (int nt = 0; nt < 4; nt++) {
                const uint32_t* base = &Bs[(kb + gc) * GBPAD + wn0 + nt * 8 + gr];
                bf[nt][0] = base[0];
                bf[nt][1] = base[4 * GBPAD];
            }
            #pragma unroll
            for (int mt = 0; mt < 4; mt++)
                #pragma unroll
                for (int nt = 0; nt < 4; nt++) {
                    asm volatile(
                        "mma.sync.aligned.m16n8k8.row.col.f32.tf32.tf32.f32 "
                        "{%0,%1,%2,%3}, {%4,%5,%6,%7}, {%8,%9}, {%0,%1,%2,%3};"
                        : "+f"(acc[mt][nt][0]), "+f"(acc[mt][nt][1]),
                          "+f"(acc[mt][nt][2]), "+f"(acc[mt][nt][3])
                        : "r"(af[mt][0]), "r"(af[mt][1]), "r"(af[mt][2]), "r"(af[mt][3]),
                          "r"(bf[nt][0]), "r"(bf[nt][1]));
                }
        }
    }

    // ---- epilogue: add bias, store ----
    #pragma unroll
    for (int mt = 0; mt < 4; mt++) {
        int r = row0 + mt * 16 + gr;
        #pragma unroll
        for (int nt = 0; nt < 4; nt++) {
            int c = col0 + wn0 + nt * 8 + 2 * gc;
            float bv0 = bias[c], bv1 = bias[c + 1];
            *(float2*)&C[(size_t)r * N + c] =
                make_float2(acc[mt][nt][0] + bv0, acc[mt][nt][1] + bv1);
            *(float2*)&C[(size_t)(r + 8) * N + c] =
                make_float2(acc[mt][nt][2] + bv0, acc[mt][nt][3] + bv1);
        }
    }
}

// ---------------------------------------------------------------------------
// TF32 tensor-core causal flash attention (exact R3 version — known good).
// ---------------------------------------------------------------------------
#define QT 128
#define KT 64
#define QPAD 68

__global__ __launch_bounds__(256, 2) void attn_tf32(
    const float* __restrict__ qkv, float* __restrict__ out)
{
    extern __shared__ uint32_t sm_u[];
    uint32_t* Qs = sm_u;
    uint32_t* Ks = Qs + QT * QPAD;
    uint32_t* Vs = Ks + KT * QPAD;
    uint32_t* Ps = Vs + KT * QPAD;

    const int tid  = threadIdx.x;
    const int lane = tid & 31;
    const int wid  = tid >> 5;
    const int gr   = lane >> 2;
    const int gc   = lane & 3;

    const int bh = blockIdx.x;
    const int b  = bh >> 4;
    const int h  = bh & 15;
    const int qi = (gridDim.y - 1) - blockIdx.y;
    const int q0 = qi * QT;
    const float scale = 0.125f;

    {
        const size_t qbase = (size_t)(b * NTOK + q0) * QKVCOLS + h * DH;
        #pragma unroll
        for (int p = 0; p < 8; p++) {
            int idx = tid + p * 256;
            int r = idx >> 4, c = (idx & 15) * 4;
            float4 v = *(const float4*)&qkv[qbase + (size_t)r * QKVCOLS + c];
            uint32_t* d = &Qs[r * QPAD + c];
            d[0] = f2tf32(v.x); d[1] = f2tf32(v.y);
            d[2] = f2tf32(v.z); d[3] = f2tf32(v.w);
        }
    }

    float accO[8][4];
    #pragma unroll
    for (int nt = 0; nt < 8; nt++)
        #pragma unroll
        for (int q = 0; q < 4; q++) accO[nt][q] = 0.f;
    float mrow[2] = { -INFINITY, -INFINITY };
    float lrow[2] = { 0.f, 0.f };

    const size_t kvbase = (size_t)(b * NTOK) * QKVCOLS + DMODEL + h * DH;
    const int nkv = 2 * qi + 2;
    const int wrow0 = q0 + wid * 16;

    for (int j = 0; j < nkv; j++) {
        __syncthreads();
        {
            #pragma unroll
            for (int p = 0; p < 4; p++) {
                int idx = tid + p * 256;
                int r = idx >> 4, c = (idx & 15) * 4;
                size_t off = kvbase + (size_t)(j * KT + r) * QKVCOLS + c;
                float4 kv4 = *(const float4*)&qkv[off];
                float4 vv4 = *(const float4*)&qkv[off + DMODEL];
                uint32_t* dk = &Ks[r * QPAD + c];
                dk[0] = f2tf32(kv4.x); dk[1] = f2tf32(kv4.y);
                dk[2] = f2tf32(kv4.z); dk[3] = f2tf32(kv4.w);
                uint32_t* dv = &Vs[r * QPAD + c];
                dv[0] = f2tf32(vv4.x); dv[1] = f2tf32(vv4.y);
                dv[2] = f2tf32(vv4.z); dv[3] = f2tf32(vv4.w);
            }
        }
        __syncthreads();

        if (j * KT > wrow0 + 15) continue;

        float s[8][4];
        #pragma unroll
        for (int nt = 0; nt < 8; nt++)
            #pragma unroll
            for (int q = 0; q < 4; q++) s[nt][q] = 0.f;

        #pragma unroll
        for (int kb = 0; kb < 8; kb++) {
            const uint32_t* abase = &Qs[(wid * 16 + gr) * QPAD + kb * 8 + gc];
            uint32_t a0 = abase[0], a1 = abase[8 * QPAD];
            uint32_t a2 = abase[4], a3 = abase[8 * QPAD + 4];
            #pragma unroll
            for (int nt = 0; nt < 8; nt++) {
                const uint32_t* bbase = &Ks[(nt * 8 + gr) * QPAD + kb * 8 + gc];
                uint32_t b0 = bbase[0], b1 = bbase[4];
                asm volatile(
                    "mma.sync.aligned.m16n8k8.row.col.f32.tf32.tf32.f32 "
                    "{%0,%1,%2,%3}, {%4,%5,%6,%7}, {%8,%9}, {%0,%1,%2,%3};"
                    : "+f"(s[nt][0]), "+f"(s[nt][1]), "+f"(s[nt][2]), "+f"(s[nt][3])
                    : "r"(a0), "r"(a1), "r"(a2), "r"(a3), "r"(b0), "r"(b1));
            }
        }

        if (j * KT + KT - 1 <= wrow0) {
            #pragma unroll
            for (int nt = 0; nt < 8; nt++)
                #pragma unroll
                for (int q = 0; q < 4; q++) s[nt][q] *= scale;
        } else {
            const int r0g = wrow0 + gr, r1g = wrow0 + gr + 8;
            #pragma unroll
            for (int nt = 0; nt < 8; nt++) {
                int c0g = j * KT + nt * 8 + 2 * gc;
                s[nt][0] = (c0g     <= r0g) ? s[nt][0] * scale : -INFINITY;
                s[nt][1] = (c0g + 1 <= r0g) ? s[nt][1] * scale : -INFINITY;
                s[nt][2] = (c0g     <= r1g) ? s[nt][2] * scale : -INFINITY;
                s[nt][3] = (c0g + 1 <= r1g) ? s[nt][3] * scale : -INFINITY;
            }
        }

        #pragma unroll
        for (int half = 0; half < 2; half++) {
            float tmax = -INFINITY;
            #pragma unroll
            for (int nt = 0; nt < 8; nt++)
                tmax = fmaxf(tmax, fmaxf(s[nt][2 * half], s[nt][2 * half + 1]));
            tmax = fmaxf(tmax, __shfl_xor_sync(0xffffffffu, tmax, 1));
            tmax = fmaxf(tmax, __shfl_xor_sync(0xffffffffu, tmax, 2));
            float mnew  = fmaxf(mrow[half], tmax);
            float alpha = __expf(mrow[half] - mnew);
            float sum = 0.f;
            const int prow = (wid * 16 + gr + 8 * half) * QPAD;
            #pragma unroll
            for (int nt = 0; nt < 8; nt++) {
                float p0 = __expf(s[nt][2 * half]     - mnew);
                float p1 = __expf(s[nt][2 * half + 1] - mnew);
                sum += p0 + p1;
                Ps[prow + nt * 8 + 2 * gc]     = f2tf32(p0);
                Ps[prow + nt * 8 + 2 * gc + 1] = f2tf32(p1);
            }
            sum += __shfl_xor_sync(0xffffffffu, sum, 1);
            sum += __shfl_xor_sync(0xffffffffu, sum, 2);
            lrow[half] = lrow[half] * alpha + sum;
            mrow[half] = mnew;
            #pragma unroll
            for (int nt = 0; nt < 8; nt++) {
                accO[nt][2 * half]     *= alpha;
                accO[nt][2 * half + 1] *= alpha;
            }
        }
        __syncwarp();

        #pragma unroll
        for (int kb = 0; kb < 8; kb++) {
            const uint32_t* abase = &Ps[(wid * 16 + gr) * QPAD + kb * 8 + gc];
            uint32_t a0 = abase[0], a1 = abase[8 * QPAD];
            uint32_t a2 = abase[4], a3 = abase[8 * QPAD + 4];
            #pragma unroll
            for (int nt = 0; nt < 8; nt++) {
                uint32_t b0 = Vs[(kb * 8 + gc) * QPAD + nt * 8 + gr];
                uint32_t b1 = Vs[(kb * 8 + gc + 4) * QPAD + nt * 8 + gr];
                asm volatile(
                    "mma.sync.aligned.m16n8k8.row.col.f32.tf32.tf32.f32 "
                    "{%0,%1,%2,%3}, {%4,%5,%6,%7}, {%8,%9}, {%0,%1,%2,%3};"
                    : "+f"(accO[nt][0]), "+f"(accO[nt][1]),
                      "+f"(accO[nt][2]), "+f"(accO[nt][3])
                    : "r"(a0), "r"(a1), "r"(a2), "r"(a3), "r"(b0), "r"(b1));
            }
        }
    }

    float inv0 = 1.f / lrow[0];
    float inv1 = 1.f / lrow[1];
    size_t r0 = (size_t)(b * NTOK + wrow0 + gr) * DMODEL + h * DH;
    size_t r1 = r0 + 8 * DMODEL;
    #pragma unroll
    for (int nt = 0; nt < 8; nt++) {
        int c = nt * 8 + 2 * gc;
        *(float2*)&out[r0 + c] = make_float2(accO[nt][0] * inv0, accO[nt][1] * inv0);
        *(float2*)&out[r1 + c] = make_float2(accO[nt][2] * inv1, accO[nt][3] * inv1);
    }
}

// ---------------------------------------------------------------------------
extern "C" void kernel_launch(void* const* d_in, const int* in_sizes, int n_in,
                              void* d_out, int out_size)
{
    const float* x     = (const float*)d_in[0];
    const float* w_qkv = (const float*)d_in[1];
    const float* b_qkv = (const float*)d_in[2];
    const float* w_out = (const float*)d_in[3];
    const float* b_out = (const float*)d_in[4];
    float* out = (float*)d_out;

    float* qkv;  cudaGetSymbolAddress((void**)&qkv, g_qkv);
    float* att;  cudaGetSymbolAddress((void**)&att, g_att);

    const int gemm_smem = (GASZ + GBSZ) * 4;     // 13568 B
    cudaFuncSetAttribute(gemm_tf32_bias,
                         cudaFuncAttributeMaxDynamicSharedMemorySize, gemm_smem);

    // 1) QKV projection (tf32, 4 CTAs/SM)
    {
        dim3 grid(QKVCOLS / 128, MROWS / 64);    // (24, 128)
        gemm_tf32_bias<<<grid, 128, gemm_smem>>>(x, w_qkv, b_qkv, qkv,
                                                 MROWS, QKVCOLS, DMODEL);
    }

    // 2) causal flash attention (tf32 mma.sync, R3-exact)
    {
        const int smem = (QT * QPAD + 2 * KT * QPAD + QT * QPAD) * 4; // 104448 B
        cudaFuncSetAttribute(attn_tf32,
                             cudaFuncAttributeMaxDynamicSharedMemorySize, smem);
        dim3 grid(BB * NH, NTOK / QT);    // (64, 16)
        attn_tf32<<<grid, 256, smem>>>(qkv, att);
    }

    // 3) output projection (tf32, 4 CTAs/SM)
    {
        dim3 grid(DMODEL / 128, MROWS / 64);     // (8, 128)
        gemm_tf32_bias<<<grid, 128, gemm_smem>>>(att, w_out, b_out, out,
                                                 MROWS, DMODEL, DMODEL);
    }
}

// round 8
// speedup vs baseline: 1.3250x; 1.0863x over previous
#include <cuda_runtime.h>
#include <math.h>
#include <stdint.h>

#define BB 4
#define NTOK 2048
#define DMODEL 1024
#define NH 16
#define DH 64
#define MROWS (BB * NTOK)            // 8192
#define QKVCOLS (3 * DMODEL)         // 3072

// Scratch (no allocations allowed)
__device__ float g_qkv[(size_t)MROWS * QKVCOLS];   // 96 MB
__device__ float g_att[(size_t)MROWS * DMODEL];    // 32 MB

__device__ __forceinline__ uint32_t f2tf32(float x) {
    uint32_t u;
    asm volatile("cvt.rna.tf32.f32 %0, %1;" : "=r"(u) : "f"(x));
    return u;
}

__device__ __forceinline__ uint32_t smem_u32(const void* p) {
    uint32_t a;
    asm("{ .reg .u64 t; cvta.to.shared.u64 t, %1; cvt.u32.u64 %0, t; }"
        : "=r"(a) : "l"(p));
    return a;
}

#define CP_ASYNC_16(dst_smem, src_gmem) \
    asm volatile("cp.async.cg.shared.global [%0], [%1], 16;" \
                 :: "r"(dst_smem), "l"(src_gmem) : "memory")
#define CP_ASYNC_COMMIT() asm volatile("cp.async.commit_group;" ::: "memory")
#define CP_ASYNC_WAIT_1() asm volatile("cp.async.wait_group 1;" ::: "memory")
#define CP_ASYNC_WAIT_0() asm volatile("cp.async.wait_group 0;" ::: "memory")

// ---------------------------------------------------------------------------
// TF32 tensor-core GEMM: R3 structure + cp.async producer.
// C[M,N] = A[M,K] @ B[K,N] + bias[N]
// CTA tile 128x128, BK=32, 256 threads (8 warps, 64x32 warp tile), 2 CTAs/SM.
// Smem holds raw fp32 (cp.async cg.128); cvt.rna at fragment load (consumer).
// Numerics bitwise-identical to R3.
// ---------------------------------------------------------------------------
#define BK 32
#define APAD 36
#define BPAD 132
#define ASTRIDE (128 * APAD)
#define BSTRIDE (BK * BPAD)

__global__ __launch_bounds__(256, 2) void gemm_tf32_bias(
    const float* __restrict__ A,
    const float* __restrict__ B,
    const float* __restrict__ bias,
    float* __restrict__ C,
    int M, int N, int K)
{
    extern __shared__ float smem_g[];
    float* As = smem_g;                    // 2 stages of 128*APAD (fp32)
    float* Bs = smem_g + 2 * ASTRIDE;      // 2 stages of BK*BPAD  (fp32)

    const int tid  = threadIdx.x;
    const int lane = tid & 31;
    const int wid  = tid >> 5;
    const int row0 = blockIdx.y * 128;
    const int col0 = blockIdx.x * 128;

    const int wm0 = (wid >> 2) * 64;
    const int wn0 = (wid & 3) * 32;
    const int gr  = lane >> 2;
    const int gc  = lane & 3;

    const int arow = tid >> 3;          // 0..31 (+p*32)
    const int acol = (tid & 7) * 4;
    const int brow = tid >> 5;          // 0..7  (+p*8)
    const int bcol = (tid & 31) * 4;

    const uint32_t sAs = smem_u32(As);
    const uint32_t sBs = smem_u32(Bs);
    const int niter = K / BK;

    // producer: issue one full stage with cp.async (8x 16B per thread)
    auto issue_stage = [&](int it) {
        const int k0 = it * BK;
        const int buf = it & 1;
        const uint32_t aBase = sAs + buf * ASTRIDE * 4;
        const uint32_t bBase = sBs + buf * BSTRIDE * 4;
        #pragma unroll
        for (int p = 0; p < 4; p++) {
            const float* ag = &A[(size_t)(row0 + arow + p * 32) * K + k0 + acol];
            CP_ASYNC_16(aBase + ((arow + p * 32) * APAD + acol) * 4, ag);
        }
        #pragma unroll
        for (int p = 0; p < 4; p++) {
            const float* bg = &B[(size_t)(k0 + brow + p * 8) * N + col0 + bcol];
            CP_ASYNC_16(bBase + ((brow + p * 8) * BPAD + bcol) * 4, bg);
        }
    };

    // prologue: stages 0 and 1 in flight
    issue_stage(0); CP_ASYNC_COMMIT();
    if (niter > 1) issue_stage(1);
    CP_ASYNC_COMMIT();

    float acc[4][4][4];
    #pragma unroll
    for (int i = 0; i < 4; i++)
        #pragma unroll
        for (int j = 0; j < 4; j++)
            #pragma unroll
            for (int q = 0; q < 4; q++) acc[i][j][q] = 0.f;

    for (int it = 0; it < niter; it++) {
        CP_ASYNC_WAIT_1();     // stage `it` landed
        __syncthreads();

        const float* Ab = As + (it & 1) * ASTRIDE;
        const float* Bb = Bs + (it & 1) * BSTRIDE;

        #pragma unroll
        for (int kk = 0; kk < 4; kk++) {
            const int kb = kk * 8;
            uint32_t af[4][4], bf[4][2];
            #pragma unroll
            for (int mt = 0; mt < 4; mt++) {
                const float* base = &Ab[(wm0 + mt * 16 + gr) * APAD + kb + gc];
                af[mt][0] = f2tf32(base[0]);
                af[mt][1] = f2tf32(base[8 * APAD]);
                af[mt][2] = f2tf32(base[4]);
                af[mt][3] = f2tf32(base[8 * APAD + 4]);
            }
            #pragma unroll
            for (int nt = 0; nt < 4; nt++) {
                const float* base = &Bb[(kb + gc) * BPAD + wn0 + nt * 8 + gr];
                bf[nt][0] = f2tf32(base[0]);
                bf[nt][1] = f2tf32(base[4 * BPAD]);
            }
            #pragma unroll
            for (int mt = 0; mt < 4; mt++)
                #pragma unroll
                for (int nt = 0; nt < 4; nt++) {
                    asm volatile(
                        "mma.sync.aligned.m16n8k8.row.col.f32.tf32.tf32.f32 "
                        "{%0,%1,%2,%3}, {%4,%5,%6,%7}, {%8,%9}, {%0,%1,%2,%3};"
                        : "+f"(acc[mt][nt][0]), "+f"(acc[mt][nt][1]),
                          "+f"(acc[mt][nt][2]), "+f"(acc[mt][nt][3])
                        : "r"(af[mt][0]), "r"(af[mt][1]), "r"(af[mt][2]), "r"(af[mt][3]),
                          "r"(bf[nt][0]), "r"(bf[nt][1]));
                }
        }

        __syncthreads();       // all warps done reading buf(it&1)
        if (it + 2 < niter) issue_stage(it + 2);
        CP_ASYNC_COMMIT();     // (possibly empty group keeps wait counts aligned)
    }

    // epilogue: add bias, store
    #pragma unroll
    for (int mt = 0; mt < 4; mt++) {
        int r = row0 + wm0 + mt * 16 + gr;
        #pragma unroll
        for (int nt = 0; nt < 4; nt++) {
            int c = col0 + wn0 + nt * 8 + 2 * gc;
            float bv0 = bias[c], bv1 = bias[c + 1];
            *(float2*)&C[(size_t)r * N + c] =
                make_float2(acc[mt][nt][0] + bv0, acc[mt][nt][1] + bv1);
            *(float2*)&C[(size_t)(r + 8) * N + c] =
                make_float2(acc[mt][nt][2] + bv0, acc[mt][nt][3] + bv1);
        }
    }
}

// ---------------------------------------------------------------------------
// TF32 tensor-core causal flash attention (exact R3 version — known good).
// ---------------------------------------------------------------------------
#define QT 128
#define KT 64
#define QPAD 68

__global__ __launch_bounds__(256, 2) void attn_tf32(
    const float* __restrict__ qkv, float* __restrict__ out)
{
    extern __shared__ uint32_t sm_u[];
    uint32_t* Qs = sm_u;
    uint32_t* Ks = Qs + QT * QPAD;
    uint32_t* Vs = Ks + KT * QPAD;
    uint32_t* Ps = Vs + KT * QPAD;

    const int tid  = threadIdx.x;
    const int lane = tid & 31;
    const int wid  = tid >> 5;
    const int gr   = lane >> 2;
    const int gc   = lane & 3;

    const int bh = blockIdx.x;
    const int b  = bh >> 4;
    const int h  = bh & 15;
    const int qi = (gridDim.y - 1) - blockIdx.y;
    const int q0 = qi * QT;
    const float scale = 0.125f;

    {
        const size_t qbase = (size_t)(b * NTOK + q0) * QKVCOLS + h * DH;
        #pragma unroll
        for (int p = 0; p < 8; p++) {
            int idx = tid + p * 256;
            int r = idx >> 4, c = (idx & 15) * 4;
            float4 v = *(const float4*)&qkv[qbase + (size_t)r * QKVCOLS + c];
            uint32_t* d = &Qs[r * QPAD + c];
            d[0] = f2tf32(v.x); d[1] = f2tf32(v.y);
            d[2] = f2tf32(v.z); d[3] = f2tf32(v.w);
        }
    }

    float accO[8][4];
    #pragma unroll
    for (int nt = 0; nt < 8; nt++)
        #pragma unroll
        for (int q = 0; q < 4; q++) accO[nt][q] = 0.f;
    float mrow[2] = { -INFINITY, -INFINITY };
    float lrow[2] = { 0.f, 0.f };

    const size_t kvbase = (size_t)(b * NTOK) * QKVCOLS + DMODEL + h * DH;
    const int nkv = 2 * qi + 2;
    const int wrow0 = q0 + wid * 16;

    for (int j = 0; j < nkv; j++) {
        __syncthreads();
        {
            #pragma unroll
            for (int p = 0; p < 4; p++) {
                int idx = tid + p * 256;
                int r = idx >> 4, c = (idx & 15) * 4;
                size_t off = kvbase + (size_t)(j * KT + r) * QKVCOLS + c;
                float4 kv4 = *(const float4*)&qkv[off];
                float4 vv4 = *(const float4*)&qkv[off + DMODEL];
                uint32_t* dk = &Ks[r * QPAD + c];
                dk[0] = f2tf32(kv4.x); dk[1] = f2tf32(kv4.y);
                dk[2] = f2tf32(kv4.z); dk[3] = f2tf32(kv4.w);
                uint32_t* dv = &Vs[r * QPAD + c];
                dv[0] = f2tf32(vv4.x); dv[1] = f2tf32(vv4.y);
                dv[2] = f2tf32(vv4.z); dv[3] = f2tf32(vv4.w);
            }
        }
        __syncthreads();

        if (j * KT > wrow0 + 15) continue;

        float s[8][4];
        #pragma unroll
        for (int nt = 0; nt < 8; nt++)
            #pragma unroll
            for (int q = 0; q < 4; q++) s[nt][q] = 0.f;

        #pragma unroll
        for (int kb = 0; kb < 8; kb++) {
            const uint32_t* abase = &Qs[(wid * 16 + gr) * QPAD + kb * 8 + gc];
            uint32_t a0 = abase[0], a1 = abase[8 * QPAD];
            uint32_t a2 = abase[4], a3 = abase[8 * QPAD + 4];
            #pragma unroll
            for (int nt = 0; nt < 8; nt++) {
                const uint32_t* bbase = &Ks[(nt * 8 + gr) * QPAD + kb * 8 + gc];
                uint32_t b0 = bbase[0], b1 = bbase[4];
                asm volatile(
                    "mma.sync.aligned.m16n8k8.row.col.f32.tf32.tf32.f32 "
                    "{%0,%1,%2,%3}, {%4,%5,%6,%7}, {%8,%9}, {%0,%1,%2,%3};"
                    : "+f"(s[nt][0]), "+f"(s[nt][1]), "+f"(s[nt][2]), "+f"(s[nt][3])
                    : "r"(a0), "r"(a1), "r"(a2), "r"(a3), "r"(b0), "r"(b1));
            }
        }

        if (j * KT + KT - 1 <= wrow0) {
            #pragma unroll
            for (int nt = 0; nt < 8; nt++)
                #pragma unroll
                for (int q = 0; q < 4; q++) s[nt][q] *= scale;
        } else {
            const int r0g = wrow0 + gr, r1g = wrow0 + gr + 8;
            #pragma unroll
            for (int nt = 0; nt < 8; nt++) {
                int c0g = j * KT + nt * 8 + 2 * gc;
                s[nt][0] = (c0g     <= r0g) ? s[nt][0] * scale : -INFINITY;
                s[nt][1] = (c0g + 1 <= r0g) ? s[nt][1] * scale : -INFINITY;
                s[nt][2] = (c0g     <= r1g) ? s[nt][2] * scale : -INFINITY;
                s[nt][3] = (c0g + 1 <= r1g) ? s[nt][3] * scale : -INFINITY;
            }
        }

        #pragma unroll
        for (int half = 0; half < 2; half++) {
            float tmax = -INFINITY;
            #pragma unroll
            for (int nt = 0; nt < 8; nt++)
                tmax = fmaxf(tmax, fmaxf(s[nt][2 * half], s[nt][2 * half + 1]));
            tmax = fmaxf(tmax, __shfl_xor_sync(0xffffffffu, tmax, 1));
            tmax = fmaxf(tmax, __shfl_xor_sync(0xffffffffu, tmax, 2));
            float mnew  = fmaxf(mrow[half], tmax);
            float alpha = __expf(mrow[half] - mnew);
            float sum = 0.f;
            const int prow = (wid * 16 + gr + 8 * half) * QPAD;
            #pragma unroll
            for (int nt = 0; nt < 8; nt++) {
                float p0 = __expf(s[nt][2 * half]     - mnew);
                float p1 = __expf(s[nt][2 * half + 1] - mnew);
                sum += p0 + p1;
                Ps[prow + nt * 8 + 2 * gc]     = f2tf32(p0);
                Ps[prow + nt * 8 + 2 * gc + 1] = f2tf32(p1);
            }
            sum += __shfl_xor_sync(0xffffffffu, sum, 1);
            sum += __shfl_xor_sync(0xffffffffu, sum, 2);
            lrow[half] = lrow[half] * alpha + sum;
            mrow[half] = mnew;
            #pragma unroll
            for (int nt = 0; nt < 8; nt++) {
                accO[nt][2 * half]     *= alpha;
                accO[nt][2 * half + 1] *= alpha;
            }
        }
        __syncwarp();

        #pragma unroll
        for (int kb = 0; kb < 8; kb++) {
            const uint32_t* abase = &Ps[(wid * 16 + gr) * QPAD + kb * 8 + gc];
            uint32_t a0 = abase[0], a1 = abase[8 * QPAD];
            uint32_t a2 = abase[4], a3 = abase[8 * QPAD + 4];
            #pragma unroll
            for (int nt = 0; nt < 8; nt++) {
                uint32_t b0 = Vs[(kb * 8 + gc) * QPAD + nt * 8 + gr];
                uint32_t b1 = Vs[(kb * 8 + gc + 4) * QPAD + nt * 8 + gr];
                asm volatile(
                    "mma.sync.aligned.m16n8k8.row.col.f32.tf32.tf32.f32 "
                    "{%0,%1,%2,%3}, {%4,%5,%6,%7}, {%8,%9}, {%0,%1,%2,%3};"
                    : "+f"(accO[nt][0]), "+f"(accO[nt][1]),
                      "+f"(accO[nt][2]), "+f"(accO[nt][3])
                    : "r"(a0), "r"(a1), "r"(a2), "r"(a3), "r"(b0), "r"(b1));
            }
        }
    }

    float inv0 = 1.f / lrow[0];
    float inv1 = 1.f / lrow[1];
    size_t r0 = (size_t)(b * NTOK + wrow0 + gr) * DMODEL + h * DH;
    size_t r1 = r0 + 8 * DMODEL;
    #pragma unroll
    for (int nt = 0; nt < 8; nt++) {
        int c = nt * 8 + 2 * gc;
        *(float2*)&out[r0 + c] = make_float2(accO[nt][0] * inv0, accO[nt][1] * inv0);
        *(float2*)&out[r1 + c] = make_float2(accO[nt][2] * inv1, accO[nt][3] * inv1);
    }
}

// ---------------------------------------------------------------------------
extern "C" void kernel_launch(void* const* d_in, const int* in_sizes, int n_in,
                              void* d_out, int out_size)
{
    const float* x     = (const float*)d_in[0];
    const float* w_qkv = (const float*)d_in[1];
    const float* b_qkv = (const float*)d_in[2];
    const float* w_out = (const float*)d_in[3];
    const float* b_out = (const float*)d_in[4];
    float* out = (float*)d_out;

    float* qkv;  cudaGetSymbolAddress((void**)&qkv, g_qkv);
    float* att;  cudaGetSymbolAddress((void**)&att, g_att);

    const int gemm_smem = (2 * ASTRIDE + 2 * BSTRIDE) * 4;   // 70656 B
    cudaFuncSetAttribute(gemm_tf32_bias,
                         cudaFuncAttributeMaxDynamicSharedMemorySize, gemm_smem);

    // 1) QKV projection (tf32, cp.async producer)
    {
        dim3 grid(QKVCOLS / 128, MROWS / 128);   // (24, 64)
        gemm_tf32_bias<<<grid, 256, gemm_smem>>>(x, w_qkv, b_qkv, qkv,
                                                 MROWS, QKVCOLS, DMODEL);
    }

    // 2) causal flash attention (tf32 mma.sync, R3-exact)
    {
        const int smem = (QT * QPAD + 2 * KT * QPAD + QT * QPAD) * 4; // 104448 B
        cudaFuncSetAttribute(attn_tf32,
                             cudaFuncAttributeMaxDynamicSharedMemorySize, smem);
        dim3 grid(BB * NH, NTOK / QT);    // (64, 16)
        attn_tf32<<<grid, 256, smem>>>(qkv, att);
    }

    // 3) output projection (tf32, cp.async producer)
    {
        dim3 grid(DMODEL / 128, MROWS / 128);    // (8, 64)
        gemm_tf32_bias<<<grid, 256, gemm_smem>>>(att, w_out, b_out, out,
                                                 MROWS, DMODEL, DMODEL);
    }
}

// round 11
// speedup vs baseline: 1.8347x; 1.3847x over previous
#include <cuda_runtime.h>
#include <cuda_fp16.h>
#include <math.h>
#include <stdint.h>

#define BB 4
#define NTOK 2048
#define DMODEL 1024
#define NH 16
#define DH 64
#define MROWS (BB * NTOK)            // 8192
#define QKVCOLS (3 * DMODEL)         // 3072

// Scratch (no allocations allowed)
__device__ float g_qkv[(size_t)MROWS * QKVCOLS];   // 96 MB
__device__ float g_att[(size_t)MROWS * DMODEL];    // 32 MB

// pack two fp32 -> f16x2 (lo = first arg)
__device__ __forceinline__ uint32_t packh2(float lo, float hi) {
    uint32_t r;
    asm("cvt.rn.f16x2.f32 %0, %1, %2;" : "=r"(r) : "f"(hi), "f"(lo));
    return r;
}

#define MMA_F16(d, a, b) \
    asm volatile( \
        "mma.sync.aligned.m16n8k16.row.col.f32.f16.f16.f32 " \
        "{%0,%1,%2,%3}, {%4,%5,%6,%7}, {%8,%9}, {%0,%1,%2,%3};" \
        : "+f"((d)[0]), "+f"((d)[1]), "+f"((d)[2]), "+f"((d)[3]) \
        : "r"((a)[0]), "r"((a)[1]), "r"((a)[2]), "r"((a)[3]), \
          "r"((b)[0]), "r"((b)[1]))

// ---------------------------------------------------------------------------
// FP16 tensor-core GEMM: C[M,N] = A[M,K] @ B[K,N] + bias[N]
// CTA tile 128x128, BK=32, 256 threads (8 warps, 64x32 warp tile), 2 CTAs/SM.
// m16n8k16 fp16 mma, fp32 accumulate. Smem fp16: Ah[m][k], Bt[n][k] (B
// transposed by producer so the col-major B fragment is a contiguous half2).
// Row stride 40 halves (80B) -> fragment LDS banks (20*gr+gc)%32 all distinct.
// ---------------------------------------------------------------------------
#define HBK 32
#define HAS 40                      // halves per A row
#define HBS 40                      // halves per Bt row
#define ASTG (128 * HAS)            // halves per A stage
#define BSTG (128 * HBS)            // halves per B stage
#define HSTAGE (ASTG + BSTG)        // halves per full stage

__global__ __launch_bounds__(256, 2) void gemm_f16_bias(
    const float* __restrict__ A,
    const float* __restrict__ B,
    const float* __restrict__ bias,
    float* __restrict__ C,
    int M, int N, int K)
{
    extern __shared__ __half smh[];

    const int tid  = threadIdx.x;
    const int lane = tid & 31;
    const int wid  = tid >> 5;
    const int row0 = blockIdx.y * 128;
    const int col0 = blockIdx.x * 128;

    const int wm0 = (wid >> 2) * 64;
    const int wn0 = (wid & 3) * 32;
    const int gr  = lane >> 2;
    const int gc  = lane & 3;

    // producer coords
    const int arow = tid >> 1;             // 0..127
    const int akq  = (tid & 1) * 16;       // k base: 0 or 16 (16 values each)
    const int bn   = tid & 127;            // 0..127
    const int bkq  = (tid >> 7) * 4;       // 0 or 4

    float aReg[16];      // 4 float4: k = akq .. akq+15
    float bReg[16];      // 4 groups of 4 strided-k values

    const int niter = K / HBK;             // 32

    auto prefetch = [&](int it) {
        const int k0 = it * HBK;
        const float* ap = &A[(size_t)(row0 + arow) * K + k0 + akq];
        *(float4*)&aReg[0]  = *(const float4*)(ap);
        *(float4*)&aReg[4]  = *(const float4*)(ap + 4);
        *(float4*)&aReg[8]  = *(const float4*)(ap + 8);
        *(float4*)&aReg[12] = *(const float4*)(ap + 12);
        #pragma unroll
        for (int j = 0; j < 4; j++) {
            const int kg = bkq + 8 * j;
            #pragma unroll
            for (int i = 0; i < 4; i++)
                bReg[4 * j + i] = B[(size_t)(k0 + kg + i) * N + col0 + bn];
        }
    };
    auto stage = [&](int buf) {
        __half* Ah = smh + buf * HSTAGE;
        __half* Bt = smh + buf * HSTAGE + ASTG;
        #pragma unroll
        for (int j = 0; j < 4; j++) {
            uint2 u;
            u.x = packh2(aReg[4 * j + 0], aReg[4 * j + 1]);
            u.y = packh2(aReg[4 * j + 2], aReg[4 * j + 3]);
            *(uint2*)&Ah[arow * HAS + akq + 4 * j] = u;
        }
        #pragma unroll
        for (int j = 0; j < 4; j++) {
            const int kg = bkq + 8 * j;
            uint2 u;
            u.x = packh2(bReg[4 * j + 0], bReg[4 * j + 1]);
            u.y = packh2(bReg[4 * j + 2], bReg[4 * j + 3]);
            *(uint2*)&Bt[bn * HBS + kg] = u;
        }
    };

    prefetch(0);
    stage(0);

    float acc[4][4][4];
    #pragma unroll
    for (int i = 0; i < 4; i++)
        #pragma unroll
        for (int j = 0; j < 4; j++)
            #pragma unroll
            for (int q = 0; q < 4; q++) acc[i][j][q] = 0.f;

    for (int it = 0; it < niter; it++) {
        __syncthreads();
        const __half* Ah = smh + (it & 1) * HSTAGE;
        const __half* Bt = smh + (it & 1) * HSTAGE + ASTG;

        if (it + 1 < niter) prefetch(it + 1);

        #pragma unroll
        for (int kk = 0; kk < 2; kk++) {     // two k16 chunks
            const int kb = kk * 16;
            uint32_t af[4][4], bf[4][2];
            #pragma unroll
            for (int mt = 0; mt < 4; mt++) {
                const __half* p = &Ah[(wm0 + mt * 16 + gr) * HAS + kb + 2 * gc];
                af[mt][0] = *(const uint32_t*)(p);
                af[mt][1] = *(const uint32_t*)(p + 8 * HAS);
                af[mt][2] = *(const uint32_t*)(p + 8);
                af[mt][3] = *(const uint32_t*)(p + 8 * HAS + 8);
            }
            #pragma unroll
            for (int nt = 0; nt < 4; nt++) {
                const __half* p = &Bt[(wn0 + nt * 8 + gr) * HBS + kb + 2 * gc];
                bf[nt][0] = *(const uint32_t*)(p);
                bf[nt][1] = *(const uint32_t*)(p + 8);
            }
            #pragma unroll
            for (int mt = 0; mt < 4; mt++)
                #pragma unroll
                for (int nt = 0; nt < 4; nt++)
                    MMA_F16(acc[mt][nt], af[mt], bf[nt]);
        }

        if (it + 1 < niter) stage((it + 1) & 1);
    }

    // epilogue: add bias, store
    #pragma unroll
    for (int mt = 0; mt < 4; mt++) {
        int r = row0 + wm0 + mt * 16 + gr;
        #pragma unroll
        for (int nt = 0; nt < 4; nt++) {
            int c = col0 + wn0 + nt * 8 + 2 * gc;
            float bv0 = bias[c], bv1 = bias[c + 1];
            *(float2*)&C[(size_t)r * N + c] =
                make_float2(acc[mt][nt][0] + bv0, acc[mt][nt][1] + bv1);
            *(float2*)&C[(size_t)(r + 8) * N + c] =
                make_float2(acc[mt][nt][2] + bv0, acc[mt][nt][3] + bv1);
        }
    }
}

// ---------------------------------------------------------------------------
// FP16 tensor-core causal flash attention (R3 structure, fp16 fragments).
// CTA = (b, h, 128-q-rows), 8 warps x 16 rows. KV tiles of 64.
// Smem fp16: Qh[128][72], Kh[64][72] (token-major), Vt[64][72] (d-major,
// transposed), Ph[128][72]. Softmax fp32 in registers.
// ---------------------------------------------------------------------------
#define QT 128
#define KT 64
#define HQS 72

__global__ __launch_bounds__(256, 2) void attn_f16(
    const float* __restrict__ qkv, float* __restrict__ out)
{
    extern __shared__ __half smA[];
    __half* Qh = smA;                        // 128*72
    __half* Kh = Qh + QT * HQS;              // 64*72
    __half* Vt = Kh + KT * HQS;              // 64*72
    __half* Ph = Vt + KT * HQS;              // 128*72

    const int tid  = threadIdx.x;
    const int lane = tid & 31;
    const int wid  = tid >> 5;
    const int gr   = lane >> 2;
    const int gc   = lane & 3;

    const int bh = blockIdx.x;
    const int b  = bh >> 4;
    const int h  = bh & 15;
    const int qi = (gridDim.y - 1) - blockIdx.y;   // heavy tiles first
    const int q0 = qi * QT;
    const float scale = 0.125f;

    // ---- load Q tile [128 x 64] -> fp16 smem ----
    {
        const size_t qbase = (size_t)(b * NTOK + q0) * QKVCOLS + h * DH;
        #pragma unroll
        for (int p = 0; p < 8; p++) {
            int idx = tid + p * 256;
            int r = idx >> 4, c = (idx & 15) * 4;
            float4 v = *(const float4*)&qkv[qbase + (size_t)r * QKVCOLS + c];
            uint2 u; u.x = packh2(v.x, v.y); u.y = packh2(v.z, v.w);
            *(uint2*)&Qh[r * HQS + c] = u;
        }
    }

    float accO[8][4];
    #pragma unroll
    for (int nt = 0; nt < 8; nt++)
        #pragma unroll
        for (int q = 0; q < 4; q++) accO[nt][q] = 0.f;
    float mrow[2] = { -INFINITY, -INFINITY };
    float lrow[2] = { 0.f, 0.f };

    const size_t kvbase = (size_t)(b * NTOK) * QKVCOLS + DMODEL + h * DH;
    const int nkv = 2 * qi + 2;
    const int wrow0 = q0 + wid * 16;

    // V-transpose producer coords
    const int vd  = tid & 63;            // d index
    const int vkg = (tid >> 6) * 4;      // kv group base

    for (int j = 0; j < nkv; j++) {
        __syncthreads();
        // ---- K tile [64 kv x 64 d], token-major fp16 ----
        #pragma unroll
        for (int p = 0; p < 4; p++) {
            int idx = tid + p * 256;
            int r = idx >> 4, c = (idx & 15) * 4;
            float4 kv4 = *(const float4*)&qkv[kvbase + (size_t)(j * KT + r) * QKVCOLS + c];
            uint2 u; u.x = packh2(kv4.x, kv4.y); u.y = packh2(kv4.z, kv4.w);
            *(uint2*)&Kh[r * HQS + c] = u;
        }
        // ---- V tile transposed -> Vt[d][kv] fp16 ----
        #pragma unroll
        for (int jj = 0; jj < 4; jj++) {
            int kv0 = vkg + 16 * jj;
            float v0 = qkv[kvbase + DMODEL + (size_t)(j * KT + kv0 + 0) * QKVCOLS + vd];
            float v1 = qkv[kvbase + DMODEL + (size_t)(j * KT + kv0 + 1) * QKVCOLS + vd];
            float v2 = qkv[kvbase + DMODEL + (size_t)(j * KT + kv0 + 2) * QKVCOLS + vd];
            float v3 = qkv[kvbase + DMODEL + (size_t)(j * KT + kv0 + 3) * QKVCOLS + vd];
            uint2 u; u.x = packh2(v0, v1); u.y = packh2(v2, v3);
            *(uint2*)&Vt[vd * HQS + kv0] = u;
        }
        __syncthreads();

        if (j * KT > wrow0 + 15) continue;

        // ---- S = Q @ K^T (16 x 64 per warp) ----
        float s[8][4];
        #pragma unroll
        for (int nt = 0; nt < 8; nt++)
            #pragma unroll
            for (int q = 0; q < 4; q++) s[nt][q] = 0.f;

        #pragma unroll
        for (int kk = 0; kk < 4; kk++) {
            const int kb = kk * 16;
            uint32_t af[4];
            const __half* qp = &Qh[(wid * 16 + gr) * HQS + kb + 2 * gc];
            af[0] = *(const uint32_t*)(qp);
            af[1] = *(const uint32_t*)(qp + 8 * HQS);
            af[2] = *(const uint32_t*)(qp + 8);
            af[3] = *(const uint32_t*)(qp + 8 * HQS + 8);
            #pragma unroll
            for (int nt = 0; nt < 8; nt++) {
                const __half* kp = &Kh[(nt * 8 + gr) * HQS + kb + 2 * gc];
                uint32_t bf[2];
                bf[0] = *(const uint32_t*)(kp);
                bf[1] = *(const uint32_t*)(kp + 8);
                MMA_F16(s[nt], af, bf);
            }
        }

        // ---- scale + causal mask ----
        if (j * KT + KT - 1 <= wrow0) {
            #pragma unroll
            for (int nt = 0; nt < 8; nt++)
                #pragma unroll
                for (int q = 0; q < 4; q++) s[nt][q] *= scale;
        } else {
            const int r0g = wrow0 + gr, r1g = wrow0 + gr + 8;
            #pragma unroll
            for (int nt = 0; nt < 8; nt++) {
                int c0g = j * KT + nt * 8 + 2 * gc;
                s[nt][0] = (c0g     <= r0g) ? s[nt][0] * scale : -INFINITY;
                s[nt][1] = (c0g + 1 <= r0g) ? s[nt][1] * scale : -INFINITY;
                s[nt][2] = (c0g     <= r1g) ? s[nt][2] * scale : -INFINITY;
                s[nt][3] = (c0g + 1 <= r1g) ? s[nt][3] * scale : -INFINITY;
            }
        }

        // ---- online softmax; write P to smem as fp16 ----
        #pragma unroll
        for (int half = 0; half < 2; half++) {
            float tmax = -INFINITY;
            #pragma unroll
            for (int nt = 0; nt < 8; nt++)
                tmax = fmaxf(tmax, fmaxf(s[nt][2 * half], s[nt][2 * half + 1]));
            tmax = fmaxf(tmax, __shfl_xor_sync(0xffffffffu, tmax, 1));
            tmax = fmaxf(tmax, __shfl_xor_sync(0xffffffffu, tmax, 2));
            float mnew  = fmaxf(mrow[half], tmax);
            float alpha = __expf(mrow[half] - mnew);
            float sum = 0.f;
            __half* prow = &Ph[(wid * 16 + gr + 8 * half) * HQS];
            #pragma unroll
            for (int nt = 0; nt < 8; nt++) {
                float p0 = __expf(s[nt][2 * half]     - mnew);
                float p1 = __expf(s[nt][2 * half + 1] - mnew);
                sum += p0 + p1;
                *(uint32_t*)&prow[nt * 8 + 2 * gc] = packh2(p0, p1);
            }
            sum += __shfl_xor_sync(0xffffffffu, sum, 1);
            sum += __shfl_xor_sync(0xffffffffu, sum, 2);
            lrow[half] = lrow[half] * alpha + sum;
            mrow[half] = mnew;
            #pragma unroll
            for (int nt = 0; nt < 8; nt++) {
                accO[nt][2 * half]     *= alpha;
                accO[nt][2 * half + 1] *= alpha;
            }
        }
        __syncwarp();

        // ---- O += P @ V ----
        #pragma unroll
        for (int kk = 0; kk < 4; kk++) {
            const int kb = kk * 16;
            uint32_t af[4];
            const __half* pp = &Ph[(wid * 16 + gr) * HQS + kb + 2 * gc];
            af[0] = *(const uint32_t*)(pp);
            af[1] = *(const uint32_t*)(pp + 8 * HQS);
            af[2] = *(const uint32_t*)(pp + 8);
            af[3] = *(const uint32_t*)(pp + 8 * HQS + 8);
            #pragma unroll
            for (int nt = 0; nt < 8; nt++) {
                const __half* vp = &Vt[(nt * 8 + gr) * HQS + kb + 2 * gc];
                uint32_t bf[2];
                bf[0] = *(const uint32_t*)(vp);
                bf[1] = *(const uint32_t*)(vp + 8);
                MMA_F16(accO[nt], af, bf);
            }
        }
    }

    // ---- epilogue: normalize, write [b, n, h*d] ----
    float inv0 = 1.f / lrow[0];
    float inv1 = 1.f / lrow[1];
    size_t r0 = (size_t)(b * NTOK + wrow0 + gr) * DMODEL + h * DH;
    size_t r1 = r0 + 8 * DMODEL;
    #pragma unroll
    for (int nt = 0; nt < 8; nt++) {
        int c = nt * 8 + 2 * gc;
        *(float2*)&out[r0 + c] = make_float2(accO[nt][0] * inv0, accO[nt][1] * inv0);
        *(float2*)&out[r1 + c] = make_float2(accO[nt][2] * inv1, accO[nt][3] * inv1);
    }
}

// ---------------------------------------------------------------------------
extern "C" void kernel_launch(void* const* d_in, const int* in_sizes, int n_in,
                              void* d_out, int out_size)
{
    const float* x     = (const float*)d_in[0];
    const float* w_qkv = (const float*)d_in[1];
    const float* b_qkv = (const float*)d_in[2];
    const float* w_out = (const float*)d_in[3];
    const float* b_out = (const float*)d_in[4];
    float* out = (float*)d_out;

    float* qkv;  cudaGetSymbolAddress((void**)&qkv, g_qkv);
    float* att;  cudaGetSymbolAddress((void**)&att, g_att);

    const int gemm_smem = 2 * HSTAGE * 2;     // 40960 B
    cudaFuncSetAttribute(gemm_f16_bias,
                         cudaFuncAttributeMaxDynamicSharedMemorySize, gemm_smem);

    // 1) QKV projection (fp16 mma)
    {
        dim3 grid(QKVCOLS / 128, MROWS / 128);   // (24, 64)
        gemm_f16_bias<<<grid, 256, gemm_smem>>>(x, w_qkv, b_qkv, qkv,
                                                MROWS, QKVCOLS, DMODEL);
    }

    // 2) causal flash attention (fp16 mma)
    {
        const int smem = (QT * HQS + 2 * KT * HQS + QT * HQS) * 2; // 55296 B
        cudaFuncSetAttribute(attn_f16,
                             cudaFuncAttributeMaxDynamicSharedMemorySize, smem);
        dim3 grid(BB * NH, NTOK / QT);    // (64, 16)
        attn_f16<<<grid, 256, smem>>>(qkv, att);
    }

    // 3) output projection (fp16 mma)
    {
        dim3 grid(DMODEL / 128, MROWS / 128);    // (8, 64)
        gemm_f16_bias<<<grid, 256, gemm_smem>>>(att, w_out, b_out, out,
                                                MROWS, DMODEL, DMODEL);
    }
}

// round 13
// speedup vs baseline: 2.4745x; 1.3487x over previous
#include <cuda_runtime.h>
#include <cuda_fp16.h>
#include <math.h>
#include <stdint.h>

#define BB 4
#define NTOK 2048
#define DMODEL 1024
#define NH 16
#define DH 64
#define MROWS (BB * NTOK)            // 8192
#define QKVCOLS (3 * DMODEL)         // 3072

// fp16 scratch (no allocations allowed)
__device__ __half g_xh[(size_t)MROWS * DMODEL];      // 16 MB
__device__ __half g_wqt[(size_t)QKVCOLS * DMODEL];   // [3072][1024] transposed
__device__ __half g_wot[(size_t)DMODEL * DMODEL];    // [1024][1024] transposed
__device__ __half g_qkvh[(size_t)MROWS * QKVCOLS];   // 48 MB
__device__ __half g_atth[(size_t)MROWS * DMODEL];    // 16 MB

// pack two fp32 -> f16x2 (lo = first arg)
__device__ __forceinline__ uint32_t packh2(float lo, float hi) {
    uint32_t r;
    asm("cvt.rn.f16x2.f32 %0, %1, %2;" : "=r"(r) : "f"(hi), "f"(lo));
    return r;
}

#define MMA_F16(d, a, b) \
    asm volatile( \
        "mma.sync.aligned.m16n8k16.row.col.f32.f16.f16.f32 " \
        "{%0,%1,%2,%3}, {%4,%5,%6,%7}, {%8,%9}, {%0,%1,%2,%3};" \
        : "+f"((d)[0]), "+f"((d)[1]), "+f"((d)[2]), "+f"((d)[3]) \
        : "r"((a)[0]), "r"((a)[1]), "r"((a)[2]), "r"((a)[3]), \
          "r"((b)[0]), "r"((b)[1]))

#define CP_ASYNC_16(dst_smem, src_gmem) \
    asm volatile("cp.async.cg.shared.global [%0], [%1], 16;" \
                 :: "r"(dst_smem), "l"(src_gmem) : "memory")
#define CP_ASYNC_COMMIT() asm volatile("cp.async.commit_group;" ::: "memory")
#define CP_ASYNC_WAIT_2() asm volatile("cp.async.wait_group 2;" ::: "memory")

__device__ __forceinline__ uint32_t smem_u32(const void* p) {
    uint32_t a;
    asm("{ .reg .u64 t; cvta.to.shared.u64 t, %1; cvt.u32.u64 %0, t; }"
        : "=r"(a) : "l"(p));
    return a;
}

// ---------------------------------------------------------------------------
// Prep kernels (run once per launch, ~25us total)
// ---------------------------------------------------------------------------
__global__ void cvt_f32_to_f16(const float* __restrict__ src,
                               __half* __restrict__ dst, int n4)
{
    int i = blockIdx.x * blockDim.x + threadIdx.x;
    if (i >= n4) return;
    float4 v = *(const float4*)&src[(size_t)i * 4];
    uint2 u; u.x = packh2(v.x, v.y); u.y = packh2(v.z, v.w);
    *(uint2*)&dst[(size_t)i * 4] = u;
}

// Wt[n][k] = (half)W[k][n], 32x32 smem tile transpose, block (32,8)
__global__ void transpose_cvt(const float* __restrict__ W,
                              __half* __restrict__ Wt, int K, int N)
{
    __shared__ float t[32][33];
    const int n0 = blockIdx.x * 32, k0 = blockIdx.y * 32;
    #pragma unroll
    for (int p = 0; p < 4; p++) {
        int k = k0 + threadIdx.y + p * 8;
        t[threadIdx.y + p * 8][threadIdx.x] = W[(size_t)k * N + n0 + threadIdx.x];
    }
    __syncthreads();
    #pragma unroll
    for (int p = 0; p < 4; p++) {
        int n = n0 + threadIdx.y + p * 8;
        Wt[(size_t)n * K + k0 + threadIdx.x] =
            __float2half_rn(t[threadIdx.x][threadIdx.y + p * 8]);
    }
}

// ---------------------------------------------------------------------------
// FP16 GEMM, 4-stage cp.async pipeline.
// C[M,N] = A[M,K] @ Bt[N,K]^T + bias[N]
// A fp16 [M,K] row-major, Bt fp16 [N,K] row-major (pre-transposed weights).
// CTA 128x128, BK=32, 256 threads, 8 warps (64x32 warp tile), 2 CTAs/SM.
// Consumer fragment layout identical to R11 (row stride 40 halves).
// ---------------------------------------------------------------------------
#define HBK 32
#define HAS 40
#define ASTG (128 * HAS)            // halves per A stage
#define STG_HALVES (2 * ASTG)       // A + B per stage
#define NSTAGE 4

template <bool OUT_HALF>
__global__ __launch_bounds__(256, 2) void gemm_f16(
    const __half* __restrict__ A,
    const __half* __restrict__ Bt,
    const float* __restrict__ bias,
    void* __restrict__ Cv,
    int M, int N, int K)
{
    extern __shared__ __half smh[];
    const uint32_t sbase = smem_u32(smh);

    const int tid  = threadIdx.x;
    const int lane = tid & 31;
    const int wid  = tid >> 5;
    const int row0 = blockIdx.y * 128;
    const int col0 = blockIdx.x * 128;

    const int wm0 = (wid >> 2) * 64;
    const int wn0 = (wid & 3) * 32;
    const int gr  = lane >> 2;
    const int gc  = lane & 3;

    const int niter = K / HBK;             // 32

    // cp.async producer: per stage 512 A-chunks + 512 B-chunks of 16B; 2+2/thread
    auto issue = [&](int it) {
        const int k0 = it * HBK;
        const uint32_t sA = sbase + (uint32_t)((it & 3) * STG_HALVES) * 2u;
        const uint32_t sB = sA + ASTG * 2u;
        #pragma unroll
        for (int p = 0; p < 2; p++) {
            int idx = tid + p * 256;
            int r = idx >> 2, c = idx & 3;         // c: 16B chunk = 8 halves
            CP_ASYNC_16(sA + (uint32_t)(r * HAS + c * 8) * 2u,
                        A + (size_t)(row0 + r) * K + k0 + c * 8);
            CP_ASYNC_16(sB + (uint32_t)(r * HAS + c * 8) * 2u,
                        Bt + (size_t)(col0 + r) * K + k0 + c * 8);
        }
    };

    // prefill 3 stages
    issue(0); CP_ASYNC_COMMIT();
    issue(1); CP_ASYNC_COMMIT();
    issue(2); CP_ASYNC_COMMIT();

    float acc[4][4][4];
    #pragma unroll
    for (int i = 0; i < 4; i++)
        #pragma unroll
        for (int j = 0; j < 4; j++)
            #pragma unroll
            for (int q = 0; q < 4; q++) acc[i][j][q] = 0.f;

    for (int it = 0; it < niter; it++) {
        CP_ASYNC_WAIT_2();          // stage `it` landed (<=2 younger pending)
        __syncthreads();            // all warps past previous compute

        if (it + 3 < niter) issue(it + 3);   // targets buf (it-1)&3: safe
        CP_ASYNC_COMMIT();

        const __half* Ah = smh + (it & 3) * STG_HALVES;
        const __half* Bh = Ah + ASTG;

        #pragma unroll
        for (int kk = 0; kk < 2; kk++) {
            const int kb = kk * 16;
            uint32_t af[4][4], bf[4][2];
            #pragma unroll
            for (int mt = 0; mt < 4; mt++) {
                const __half* p = &Ah[(wm0 + mt * 16 + gr) * HAS + kb + 2 * gc];
                af[mt][0] = *(const uint32_t*)(p);
                af[mt][1] = *(const uint32_t*)(p + 8 * HAS);
                af[mt][2] = *(const uint32_t*)(p + 8);
                af[mt][3] = *(const uint32_t*)(p + 8 * HAS + 8);
            }
            #pragma unroll
            for (int nt = 0; nt < 4; nt++) {
                const __half* p = &Bh[(wn0 + nt * 8 + gr) * HAS + kb + 2 * gc];
                bf[nt][0] = *(const uint32_t*)(p);
                bf[nt][1] = *(const uint32_t*)(p + 8);
            }
            #pragma unroll
            for (int mt = 0; mt < 4; mt++)
                #pragma unroll
                for (int nt = 0; nt < 4; nt++)
                    MMA_F16(acc[mt][nt], af[mt], bf[nt]);
        }
    }

    // epilogue: add bias, store (fp16 or fp32)
    #pragma unroll
    for (int mt = 0; mt < 4; mt++) {
        int r = row0 + wm0 + mt * 16 + gr;
        #pragma unroll
        for (int nt = 0; nt < 4; nt++) {
            int c = col0 + wn0 + nt * 8 + 2 * gc;
            float bv0 = bias[c], bv1 = bias[c + 1];
            if (OUT_HALF) {
                __half* C = (__half*)Cv;
                *(uint32_t*)&C[(size_t)r * N + c] =
                    packh2(acc[mt][nt][0] + bv0, acc[mt][nt][1] + bv1);
                *(uint32_t*)&C[(size_t)(r + 8) * N + c] =
                    packh2(acc[mt][nt][2] + bv0, acc[mt][nt][3] + bv1);
            } else {
                float* C = (float*)Cv;
                *(float2*)&C[(size_t)r * N + c] =
                    make_float2(acc[mt][nt][0] + bv0, acc[mt][nt][1] + bv1);
                *(float2*)&C[(size_t)(r + 8) * N + c] =
                    make_float2(acc[mt][nt][2] + bv0, acc[mt][nt][3] + bv1);
            }
        }
    }
}

// ---------------------------------------------------------------------------
// FP16 causal flash attention, fp16 in / fp16 out (R11 structure).
// ---------------------------------------------------------------------------
#define QT 128
#define KT 64
#define HQS 72

__global__ __launch_bounds__(256, 2) void attn_f16(
    const __half* __restrict__ qkv, __half* __restrict__ out)
{
    extern __shared__ __half smA[];
    __half* Qh = smA;                        // 128*72
    __half* Kh = Qh + QT * HQS;              // 64*72
    __half* Vt = Kh + KT * HQS;              // 64*72
    __half* Ph = Vt + KT * HQS;              // 128*72

    const int tid  = threadIdx.x;
    const int lane = tid & 31;
    const int wid  = tid >> 5;
    const int gr   = lane >> 2;
    const int gc   = lane & 3;

    const int bh = blockIdx.x;
    const int b  = bh >> 4;
    const int h  = bh & 15;
    const int qi = (gridDim.y - 1) - blockIdx.y;   // heavy tiles first
    const int q0 = qi * QT;
    const float scale = 0.125f;

    // ---- load Q tile [128 x 64] fp16 -> smem ----
    {
        const size_t qbase = (size_t)(b * NTOK + q0) * QKVCOLS + h * DH;
        #pragma unroll
        for (int p = 0; p < 8; p++) {
            int idx = tid + p * 256;
            int r = idx >> 4, c = (idx & 15) * 4;
            *(uint2*)&Qh[r * HQS + c] =
                *(const uint2*)&qkv[qbase + (size_t)r * QKVCOLS + c];
        }
    }

    float accO[8][4];
    #pragma unroll
    for (int nt = 0; nt < 8; nt++)
        #pragma unroll
        for (int q = 0; q < 4; q++) accO[nt][q] = 0.f;
    float mrow[2] = { -INFINITY, -INFINITY };
    float lrow[2] = { 0.f, 0.f };

    const size_t kvbase = (size_t)(b * NTOK) * QKVCOLS + DMODEL + h * DH;
    const int nkv = 2 * qi + 2;
    const int wrow0 = q0 + wid * 16;

    // V-transpose producer coords
    const int vd  = tid & 63;            // d index
    const int vkg = (tid >> 6) * 4;      // kv group base

    for (int j = 0; j < nkv; j++) {
        __syncthreads();
        // ---- K tile [64 kv x 64 d] fp16, token-major ----
        #pragma unroll
        for (int p = 0; p < 4; p++) {
            int idx = tid + p * 256;
            int r = idx >> 4, c = (idx & 15) * 4;
            *(uint2*)&Kh[r * HQS + c] =
                *(const uint2*)&qkv[kvbase + (size_t)(j * KT + r) * QKVCOLS + c];
        }
        // ---- V tile transposed -> Vt[d][kv] fp16 ----
        #pragma unroll
        for (int jj = 0; jj < 4; jj++) {
            int kv0 = vkg + 16 * jj;
            const __half* vp0 = &qkv[kvbase + DMODEL + (size_t)(j * KT + kv0) * QKVCOLS + vd];
            __half v0 = vp0[0];
            __half v1 = vp0[QKVCOLS];
            __half v2 = vp0[2 * QKVCOLS];
            __half v3 = vp0[3 * QKVCOLS];
            uint2 u;
            u.x = (uint32_t)__half_as_ushort(v0) | ((uint32_t)__half_as_ushort(v1) << 16);
            u.y = (uint32_t)__half_as_ushort(v2) | ((uint32_t)__half_as_ushort(v3) << 16);
            *(uint2*)&Vt[vd * HQS + kv0] = u;
        }
        __syncthreads();

        if (j * KT > wrow0 + 15) continue;

        // ---- S = Q @ K^T (16 x 64 per warp) ----
        float s[8][4];
        #pragma unroll
        for (int nt = 0; nt < 8; nt++)
            #pragma unroll
            for (int q = 0; q < 4; q++) s[nt][q] = 0.f;

        #pragma unroll
        for (int kk = 0; kk < 4; kk++) {
            const int kb = kk * 16;
            uint32_t af[4];
            const __half* qp = &Qh[(wid * 16 + gr) * HQS + kb + 2 * gc];
            af[0] = *(const uint32_t*)(qp);
            af[1] = *(const uint32_t*)(qp + 8 * HQS);
            af[2] = *(const uint32_t*)(qp + 8);
            af[3] = *(const uint32_t*)(qp + 8 * HQS + 8);
            #pragma unroll
            for (int nt = 0; nt < 8; nt++) {
                const __half* kp = &Kh[(nt * 8 + gr) * HQS + kb + 2 * gc];
                uint32_t bf[2];
                bf[0] = *(const uint32_t*)(kp);
                bf[1] = *(const uint32_t*)(kp + 8);
                MMA_F16(s[nt], af, bf);
            }
        }

        // ---- scale + causal mask ----
        if (j * KT + KT - 1 <= wrow0) {
            #pragma unroll
            for (int nt = 0; nt < 8; nt++)
                #pragma unroll
                for (int q = 0; q < 4; q++) s[nt][q] *= scale;
        } else {
            const int r0g = wrow0 + gr, r1g = wrow0 + gr + 8;
            #pragma unroll
            for (int nt = 0; nt < 8; nt++) {
                int c0g = j * KT + nt * 8 + 2 * gc;
                s[nt][0] = (c0g     <= r0g) ? s[nt][0] * scale : -INFINITY;
                s[nt][1] = (c0g + 1 <= r0g) ? s[nt][1] * scale : -INFINITY;
                s[nt][2] = (c0g     <= r1g) ? s[nt][2] * scale : -INFINITY;
                s[nt][3] = (c0g + 1 <= r1g) ? s[nt][3] * scale : -INFINITY;
            }
        }

        // ---- online softmax; write P to smem as fp16 ----
        #pragma unroll
        for (int half = 0; half < 2; half++) {
            float tmax = -INFINITY;
            #pragma unroll
            for (int nt = 0; nt < 8; nt++)
                tmax = fmaxf(tmax, fmaxf(s[nt][2 * half], s[nt][2 * half + 1]));
            tmax = fmaxf(tmax, __shfl_xor_sync(0xffffffffu, tmax, 1));
            tmax = fmaxf(tmax, __shfl_xor_sync(0xffffffffu, tmax, 2));
            float mnew  = fmaxf(mrow[half], tmax);
            float alpha = __expf(mrow[half] - mnew);
            float sum = 0.f;
            __half* prow = &Ph[(wid * 16 + gr + 8 * half) * HQS];
            #pragma unroll
            for (int nt = 0; nt < 8; nt++) {
                float p0 = __expf(s[nt][2 * half]     - mnew);
                float p1 = __expf(s[nt][2 * half + 1] - mnew);
                sum += p0 + p1;
                *(uint32_t*)&prow[nt * 8 + 2 * gc] = packh2(p0, p1);
            }
            sum += __shfl_xor_sync(0xffffffffu, sum, 1);
            sum += __shfl_xor_sync(0xffffffffu, sum, 2);
            lrow[half] = lrow[half] * alpha + sum;
            mrow[half] = mnew;
            #pragma unroll
            for (int nt = 0; nt < 8; nt++) {
                accO[nt][2 * half]     *= alpha;
                accO[nt][2 * half + 1] *= alpha;
            }
        }
        __syncwarp();

        // ---- O += P @ V ----
        #pragma unroll
        for (int kk = 0; kk < 4; kk++) {
            const int kb = kk * 16;
            uint32_t af[4];
            const __half* pp = &Ph[(wid * 16 + gr) * HQS + kb + 2 * gc];
            af[0] = *(const uint32_t*)(pp);
            af[1] = *(const uint32_t*)(pp + 8 * HQS);
            af[2] = *(const uint32_t*)(pp + 8);
            af[3] = *(const uint32_t*)(pp + 8 * HQS + 8);
            #pragma unroll
            for (int nt = 0; nt < 8; nt++) {
                const __half* vp = &Vt[(nt * 8 + gr) * HQS + kb + 2 * gc];
                uint32_t bf[2];
                bf[0] = *(const uint32_t*)(vp);
                bf[1] = *(const uint32_t*)(vp + 8);
                MMA_F16(accO[nt], af, bf);
            }
        }
    }

    // ---- epilogue: normalize, write fp16 [b, n, h*d] ----
    float inv0 = 1.f / lrow[0];
    float inv1 = 1.f / lrow[1];
    size_t r0 = (size_t)(b * NTOK + wrow0 + gr) * DMODEL + h * DH;
    size_t r1 = r0 + 8 * DMODEL;
    #pragma unroll
    for (int nt = 0; nt < 8; nt++) {
        int c = nt * 8 + 2 * gc;
        *(uint32_t*)&out[r0 + c] = packh2(accO[nt][0] * inv0, accO[nt][1] * inv0);
        *(uint32_t*)&out[r1 + c] = packh2(accO[nt][2] * inv1, accO[nt][3] * inv1);
    }
}

// ---------------------------------------------------------------------------
extern "C" void kernel_launch(void* const* d_in, const int* in_sizes, int n_in,
                              void* d_out, int out_size)
{
    const float* x     = (const float*)d_in[0];
    const float* w_qkv = (const float*)d_in[1];
    const float* b_qkv = (const float*)d_in[2];
    const float* w_out = (const float*)d_in[3];
    const float* b_out = (const float*)d_in[4];
    float* out = (float*)d_out;

    __half* xh;    cudaGetSymbolAddress((void**)&xh,   g_xh);
    __half* wqt;   cudaGetSymbolAddress((void**)&wqt,  g_wqt);
    __half* wot;   cudaGetSymbolAddress((void**)&wot,  g_wot);
    __half* qkvh;  cudaGetSymbolAddress((void**)&qkvh, g_qkvh);
    __half* atth;  cudaGetSymbolAddress((void**)&atth, g_atth);

    // 0) prep: convert x, transpose-convert weights to fp16
    {
        int n4 = MROWS * DMODEL / 4;                   // 2,097,152
        cvt_f32_to_f16<<<(n4 + 255) / 256, 256>>>(x, xh, n4);
        dim3 blk(32, 8);
        transpose_cvt<<<dim3(QKVCOLS / 32, DMODEL / 32), blk>>>(w_qkv, wqt,
                                                                DMODEL, QKVCOLS);
        transpose_cvt<<<dim3(DMODEL / 32, DMODEL / 32), blk>>>(w_out, wot,
                                                               DMODEL, DMODEL);
    }

    const int gemm_smem = NSTAGE * STG_HALVES * 2;     // 81920 B
    cudaFuncSetAttribute(gemm_f16<true>,
                         cudaFuncAttributeMaxDynamicSharedMemorySize, gemm_smem);
    cudaFuncSetAttribute(gemm_f16<false>,
                         cudaFuncAttributeMaxDynamicSharedMemorySize, gemm_smem);

    // 1) QKV projection (fp16 in/out, cp.async pipeline)
    {
        dim3 grid(QKVCOLS / 128, MROWS / 128);   // (24, 64)
        gemm_f16<true><<<grid, 256, gemm_smem>>>(xh, wqt, b_qkv, qkvh,
                                                 MROWS, QKVCOLS, DMODEL);
    }

    // 2) causal flash attention (fp16 in/out)
    {
        const int smem = (QT * HQS + 2 * KT * HQS + QT * HQS) * 2; // 55296 B
        cudaFuncSetAttribute(attn_f16,
                             cudaFuncAttributeMaxDynamicSharedMemorySize, smem);
        dim3 grid(BB * NH, NTOK / QT);    // (64, 16)
        attn_f16<<<grid, 256, smem>>>(qkvh, atth);
    }

    // 3) output projection (fp16 in, fp32 out)
    {
        dim3 grid(DMODEL / 128, MROWS / 128);    // (8, 64)
        gemm_f16<false><<<grid, 256, gemm_smem>>>(atth, wot, b_out, out,
                                                  MROWS, DMODEL, DMODEL);
    }
}

// round 16
// speedup vs baseline: 2.7228x; 1.1004x over previous
#include <cuda_runtime.h>
#include <cuda_fp16.h>
#include <math.h>
#include <stdint.h>

#define BB 4
#define NTOK 2048
#define DMODEL 1024
#define NH 16
#define DH 64
#define MROWS (BB * NTOK)            // 8192
#define QKVCOLS (3 * DMODEL)         // 3072

// fp16 scratch (no allocations allowed)
__device__ __half g_xh[(size_t)MROWS * DMODEL];      // 16 MB
__device__ __half g_wqt[(size_t)QKVCOLS * DMODEL];   // [3072][1024] transposed
__device__ __half g_wot[(size_t)DMODEL * DMODEL];    // [1024][1024] transposed
__device__ __half g_qkvh[(size_t)MROWS * QKVCOLS];   // 48 MB
__device__ __half g_atth[(size_t)MROWS * DMODEL];    // 16 MB

// pack two fp32 -> f16x2 (lo = first arg)
__device__ __forceinline__ uint32_t packh2(float lo, float hi) {
    uint32_t r;
    asm("cvt.rn.f16x2.f32 %0, %1, %2;" : "=r"(r) : "f"(hi), "f"(lo));
    return r;
}

#define MMA_F16(d, a, b) \
    asm volatile( \
        "mma.sync.aligned.m16n8k16.row.col.f32.f16.f16.f32 " \
        "{%0,%1,%2,%3}, {%4,%5,%6,%7}, {%8,%9}, {%0,%1,%2,%3};" \
        : "+f"((d)[0]), "+f"((d)[1]), "+f"((d)[2]), "+f"((d)[3]) \
        : "r"((a)[0]), "r"((a)[1]), "r"((a)[2]), "r"((a)[3]), \
          "r"((b)[0]), "r"((b)[1]))

#define CP_ASYNC_16(dst_smem, src_gmem) \
    asm volatile("cp.async.cg.shared.global [%0], [%1], 16;" \
                 :: "r"(dst_smem), "l"(src_gmem) : "memory")
#define CP_ASYNC_COMMIT() asm volatile("cp.async.commit_group;" ::: "memory")
#define CP_ASYNC_WAIT_2() asm volatile("cp.async.wait_group 2;" ::: "memory")

__device__ __forceinline__ uint32_t smem_u32(const void* p) {
    uint32_t a;
    asm("{ .reg .u64 t; cvta.to.shared.u64 t, %1; cvt.u32.u64 %0, t; }"
        : "=r"(a) : "l"(p));
    return a;
}

#define LDSM_X4(r0, r1, r2, r3, addr) \
    asm volatile("ldmatrix.sync.aligned.m8n8.x4.shared.b16 {%0,%1,%2,%3}, [%4];" \
                 : "=r"(r0), "=r"(r1), "=r"(r2), "=r"(r3) : "r"(addr))

// ---------------------------------------------------------------------------
// Prep kernels (run once per launch, ~25us total)
// ---------------------------------------------------------------------------
__global__ void cvt_f32_to_f16(const float* __restrict__ src,
                               __half* __restrict__ dst, int n4)
{
    int i = blockIdx.x * blockDim.x + threadIdx.x;
    if (i >= n4) return;
    float4 v = *(const float4*)&src[(size_t)i * 4];
    uint2 u; u.x = packh2(v.x, v.y); u.y = packh2(v.z, v.w);
    *(uint2*)&dst[(size_t)i * 4] = u;
}

// Wt[n][k] = (half)W[k][n], 32x32 smem tile transpose, block (32,8)
__global__ void transpose_cvt(const float* __restrict__ W,
                              __half* __restrict__ Wt, int K, int N)
{
    __shared__ float t[32][33];
    const int n0 = blockIdx.x * 32, k0 = blockIdx.y * 32;
    #pragma unroll
    for (int p = 0; p < 4; p++) {
        int k = k0 + threadIdx.y + p * 8;
        t[threadIdx.y + p * 8][threadIdx.x] = W[(size_t)k * N + n0 + threadIdx.x];
    }
    __syncthreads();
    #pragma unroll
    for (int p = 0; p < 4; p++) {
        int n = n0 + threadIdx.y + p * 8;
        Wt[(size_t)n * K + k0 + threadIdx.x] =
            __float2half_rn(t[threadIdx.x][threadIdx.y + p * 8]);
    }
}

// ---------------------------------------------------------------------------
// FP16 GEMM, 4-stage cp.async pipeline, ldmatrix fragment loads.
// C[M,N] = A[M,K] @ Bt[N,K]^T + bias[N]
// CTA 128x128, BK=32, 256 threads, 8 warps (64x32 warp tile), 2 CTAs/SM.
// ---------------------------------------------------------------------------
#define HBK 32
#define HAS 40
#define ASTG (128 * HAS)            // halves per A stage
#define STG_HALVES (2 * ASTG)       // A + B per stage
#define NSTAGE 4

template <bool OUT_HALF>
__global__ __launch_bounds__(256, 2) void gemm_f16(
    const __half* __restrict__ A,
    const __half* __restrict__ Bt,
    const float* __restrict__ bias,
    void* __restrict__ Cv,
    int M, int N, int K)
{
    extern __shared__ __half smh[];
    const uint32_t sbase = smem_u32(smh);

    const int tid  = threadIdx.x;
    const int lane = tid & 31;
    const int wid  = tid >> 5;
    const int row0 = blockIdx.y * 128;
    const int col0 = blockIdx.x * 128;

    const int wm0 = (wid >> 2) * 64;
    const int wn0 = (wid & 3) * 32;
    const int gr  = lane >> 2;
    const int gc  = lane & 3;

    // ldmatrix source coords (within a 16-row x 16-col tile)
    const int a_r = (lane & 7) + ((lane >> 3) & 1) * 8;   // A/P: m-row
    const int a_c = (lane >> 4) * 8;                      // A/P: k-col
    const int b_r = (lane & 7) + ((lane >> 4) & 1) * 8;   // B: n-row
    const int b_c = ((lane >> 3) & 1) * 8;                // B: k-col

    const int niter = K / HBK;             // 32

    // cp.async producer: 2 A + 2 B chunks of 16B per thread per stage
    auto issue = [&](int it) {
        const int k0 = it * HBK;
        const uint32_t sA = sbase + (uint32_t)((it & 3) * STG_HALVES) * 2u;
        const uint32_t sB = sA + ASTG * 2u;
        #pragma unroll
        for (int p = 0; p < 2; p++) {
            int idx = tid + p * 256;
            int r = idx >> 2, c = idx & 3;
            CP_ASYNC_16(sA + (uint32_t)(r * HAS + c * 8) * 2u,
                        A + (size_t)(row0 + r) * K + k0 + c * 8);
            CP_ASYNC_16(sB + (uint32_t)(r * HAS + c * 8) * 2u,
                        Bt + (size_t)(col0 + r) * K + k0 + c * 8);
        }
    };

    issue(0); CP_ASYNC_COMMIT();
    issue(1); CP_ASYNC_COMMIT();
    issue(2); CP_ASYNC_COMMIT();

    float acc[4][4][4];
    #pragma unroll
    for (int i = 0; i < 4; i++)
        #pragma unroll
        for (int j = 0; j < 4; j++)
            #pragma unroll
            for (int q = 0; q < 4; q++) acc[i][j][q] = 0.f;

    for (int it = 0; it < niter; it++) {
        CP_ASYNC_WAIT_2();
        __syncthreads();

        if (it + 3 < niter) issue(it + 3);
        CP_ASYNC_COMMIT();

        const uint32_t stg = sbase + (uint32_t)((it & 3) * STG_HALVES) * 2u;
        const uint32_t aAddr = stg + (uint32_t)((wm0 + a_r) * HAS + a_c) * 2u;
        const uint32_t bAddr = stg + (uint32_t)(ASTG + (wn0 + b_r) * HAS + b_c) * 2u;

        #pragma unroll
        for (int kk = 0; kk < 2; kk++) {
            const uint32_t kOff = (uint32_t)(kk * 16) * 2u;
            uint32_t af[4][4], bf[4][2];
            #pragma unroll
            for (int mt = 0; mt < 4; mt++)
                LDSM_X4(af[mt][0], af[mt][1], af[mt][2], af[mt][3],
                        aAddr + (uint32_t)(mt * 16 * HAS) * 2u + kOff);
            #pragma unroll
            for (int p = 0; p < 2; p++)
                LDSM_X4(bf[2 * p][0], bf[2 * p][1], bf[2 * p + 1][0], bf[2 * p + 1][1],
                        bAddr + (uint32_t)(p * 16 * HAS) * 2u + kOff);
            #pragma unroll
            for (int mt = 0; mt < 4; mt++)
                #pragma unroll
                for (int nt = 0; nt < 4; nt++)
                    MMA_F16(acc[mt][nt], af[mt], bf[nt]);
        }
    }

    // epilogue: add bias, store (fp16 or fp32)
    #pragma unroll
    for (int mt = 0; mt < 4; mt++) {
        int r = row0 + wm0 + mt * 16 + gr;
        #pragma unroll
        for (int nt = 0; nt < 4; nt++) {
            int c = col0 + wn0 + nt * 8 + 2 * gc;
            float bv0 = bias[c], bv1 = bias[c + 1];
            if (OUT_HALF) {
                __half* C = (__half*)Cv;
                *(uint32_t*)&C[(size_t)r * N + c] =
                    packh2(acc[mt][nt][0] + bv0, acc[mt][nt][1] + bv1);
                *(uint32_t*)&C[(size_t)(r + 8) * N + c] =
                    packh2(acc[mt][nt][2] + bv0, acc[mt][nt][3] + bv1);
            } else {
                float* C = (float*)Cv;
                *(float2*)&C[(size_t)r * N + c] =
                    make_float2(acc[mt][nt][0] + bv0, acc[mt][nt][1] + bv1);
                *(float2*)&C[(size_t)(r + 8) * N + c] =
                    make_float2(acc[mt][nt][2] + bv0, acc[mt][nt][3] + bv1);
            }
        }
    }
}

// ---------------------------------------------------------------------------
// FP16 causal flash attention, ldmatrix fragment loads.
// ---------------------------------------------------------------------------
#define QT 128
#define KT 64
#define HQS 72

__global__ __launch_bounds__(256, 2) void attn_f16(
    const __half* __restrict__ qkv, __half* __restrict__ out)
{
    extern __shared__ __half smA[];
    __half* Qh = smA;                        // 128*72
    __half* Kh = Qh + QT * HQS;              // 64*72
    __half* Vt = Kh + KT * HQS;              // 64*72
    __half* Ph = Vt + KT * HQS;              // 128*72

    const int tid  = threadIdx.x;
    const int lane = tid & 31;
    const int wid  = tid >> 5;
    const int gr   = lane >> 2;
    const int gc   = lane & 3;

    const int a_r = (lane & 7) + ((lane >> 3) & 1) * 8;
    const int a_c = (lane >> 4) * 8;
    const int b_r = (lane & 7) + ((lane >> 4) & 1) * 8;
    const int b_c = ((lane >> 3) & 1) * 8;

    const int bh = blockIdx.x;
    const int b  = bh >> 4;
    const int h  = bh & 15;
    const int qi = (gridDim.y - 1) - blockIdx.y;   // heavy tiles first
    const int q0 = qi * QT;
    const float scale = 0.125f;

    // ---- load Q tile [128 x 64] fp16 -> smem ----
    {
        const size_t qbase = (size_t)(b * NTOK + q0) * QKVCOLS + h * DH;
        #pragma unroll
        for (int p = 0; p < 8; p++) {
            int idx = tid + p * 256;
            int r = idx >> 4, c = (idx & 15) * 4;
            *(uint2*)&Qh[r * HQS + c] =
                *(const uint2*)&qkv[qbase + (size_t)r * QKVCOLS + c];
        }
    }

    float accO[8][4];
    #pragma unroll
    for (int nt = 0; nt < 8; nt++)
        #pragma unroll
        for (int q = 0; q < 4; q++) accO[nt][q] = 0.f;
    float mrow[2] = { -INFINITY, -INFINITY };
    float lrow[2] = { 0.f, 0.f };

    const size_t kvbase = (size_t)(b * NTOK) * QKVCOLS + DMODEL + h * DH;
    const int nkv = 2 * qi + 2;
    const int wrow0 = q0 + wid * 16;

    const uint32_t qAddr = smem_u32(&Qh[(wid * 16 + a_r) * HQS + a_c]);
    const uint32_t kAddr = smem_u32(&Kh[b_r * HQS + b_c]);
    const uint32_t vAddr = smem_u32(&Vt[b_r * HQS + b_c]);
    const uint32_t pAddr = smem_u32(&Ph[(wid * 16 + a_r) * HQS + a_c]);

    // V-transpose producer coords
    const int vd  = tid & 63;            // d index
    const int vkg = (tid >> 6) * 4;      // kv group base

    for (int j = 0; j < nkv; j++) {
        __syncthreads();
        // ---- K tile [64 kv x 64 d] fp16, token-major ----
        #pragma unroll
        for (int p = 0; p < 4; p++) {
            int idx = tid + p * 256;
            int r = idx >> 4, c = (idx & 15) * 4;
            *(uint2*)&Kh[r * HQS + c] =
                *(const uint2*)&qkv[kvbase + (size_t)(j * KT + r) * QKVCOLS + c];
        }
        // ---- V tile transposed -> Vt[d][kv] fp16 ----
        #pragma unroll
        for (int jj = 0; jj < 4; jj++) {
            int kv0 = vkg + 16 * jj;
            const __half* vp0 = &qkv[kvbase + DMODEL + (size_t)(j * KT + kv0) * QKVCOLS + vd];
            __half v0 = vp0[0];
            __half v1 = vp0[QKVCOLS];
            __half v2 = vp0[2 * QKVCOLS];
            __half v3 = vp0[3 * QKVCOLS];
            uint2 u;
            u.x = (uint32_t)__half_as_ushort(v0) | ((uint32_t)__half_as_ushort(v1) << 16);
            u.y = (uint32_t)__half_as_ushort(v2) | ((uint32_t)__half_as_ushort(v3) << 16);
            *(uint2*)&Vt[vd * HQS + kv0] = u;
        }
        __syncthreads();

        if (j * KT > wrow0 + 15) continue;

        // ---- S = Q @ K^T (16 x 64 per warp) ----
        float s[8][4];
        #pragma unroll
        for (int nt = 0; nt < 8; nt++)
            #pragma unroll
            for (int q = 0; q < 4; q++) s[nt][q] = 0.f;

        #pragma unroll
        for (int kk = 0; kk < 4; kk++) {
            const uint32_t kOff = (uint32_t)(kk * 16) * 2u;
            uint32_t af[4];
            LDSM_X4(af[0], af[1], af[2], af[3], qAddr + kOff);
            #pragma unroll
            for (int p = 0; p < 4; p++) {
                uint32_t bf0[2], bf1[2];
                LDSM_X4(bf0[0], bf0[1], bf1[0], bf1[1],
                        kAddr + (uint32_t)(p * 16 * HQS) * 2u + kOff);
                MMA_F16(s[2 * p],     af, bf0);
                MMA_F16(s[2 * p + 1], af, bf1);
            }
        }

        // ---- scale + causal mask ----
        if (j * KT + KT - 1 <= wrow0) {
            #pragma unroll
            for (int nt = 0; nt < 8; nt++)
                #pragma unroll
                for (int q = 0; q < 4; q++) s[nt][q] *= scale;
        } else {
            const int r0g = wrow0 + gr, r1g = wrow0 + gr + 8;
            #pragma unroll
            for (int nt = 0; nt < 8; nt++) {
                int c0g = j * KT + nt * 8 + 2 * gc;
                s[nt][0] = (c0g     <= r0g) ? s[nt][0] * scale : -INFINITY;
                s[nt][1] = (c0g + 1 <= r0g) ? s[nt][1] * scale : -INFINITY;
                s[nt][2] = (c0g     <= r1g) ? s[nt][2] * scale : -INFINITY;
                s[nt][3] = (c0g + 1 <= r1g) ? s[nt][3] * scale : -INFINITY;
            }
        }

        // ---- online softmax; write P to smem as fp16 ----
        #pragma unroll
        for (int half = 0; half < 2; half++) {
            float tmax = -INFINITY;
            #pragma unroll
            for (int nt = 0; nt < 8; nt++)
                tmax = fmaxf(tmax, fmaxf(s[nt][2 * half], s[nt][2 * half + 1]));
            tmax = fmaxf(tmax, __shfl_xor_sync(0xffffffffu, tmax, 1));
            tmax = fmaxf(tmax, __shfl_xor_sync(0xffffffffu, tmax, 2));
            float mnew  = fmaxf(mrow[half], tmax);
            float alpha = __expf(mrow[half] - mnew);
            float sum = 0.f;
            __half* prow = &Ph[(wid * 16 + gr + 8 * half) * HQS];
            #pragma unroll
            for (int nt = 0; nt < 8; nt++) {
                float p0 = __expf(s[nt][2 * half]     - mnew);
                float p1 = __expf(s[nt][2 * half + 1] - mnew);
                sum += p0 + p1;
                *(uint32_t*)&prow[nt * 8 + 2 * gc] = packh2(p0, p1);
            }
            sum += __shfl_xor_sync(0xffffffffu, sum, 1);
            sum += __shfl_xor_sync(0xffffffffu, sum, 2);
            lrow[half] = lrow[half] * alpha + sum;
            mrow[half] = mnew;
            #pragma unroll
            for (int nt = 0; nt < 8; nt++) {
                accO[nt][2 * half]     *= alpha;
                accO[nt][2 * half + 1] *= alpha;
            }
        }
        __syncwarp();

        // ---- O += P @ V ----
        #pragma unroll
        for (int kk = 0; kk < 4; kk++) {
            const uint32_t kOff = (uint32_t)(kk * 16) * 2u;
            uint32_t af[4];
            LDSM_X4(af[0], af[1], af[2], af[3], pAddr + kOff);
            #pragma unroll
            for (int p = 0; p < 4; p++) {
                uint32_t bf0[2], bf1[2];
                LDSM_X4(bf0[0], bf0[1], bf1[0], bf1[1],
                        vAddr + (uint32_t)(p * 16 * HQS) * 2u + kOff);
                MMA_F16(accO[2 * p],     af, bf0);
                MMA_F16(accO[2 * p + 1], af, bf1);
            }
        }
    }

    // ---- epilogue: normalize, write fp16 [b, n, h*d] ----
    float inv0 = 1.f / lrow[0];
    float inv1 = 1.f / lrow[1];
    size_t r0 = (size_t)(b * NTOK + wrow0 + gr) * DMODEL + h * DH;
    size_t r1 = r0 + 8 * DMODEL;
    #pragma unroll
    for (int nt = 0; nt < 8; nt++) {
        int c = nt * 8 + 2 * gc;
        *(uint32_t*)&out[r0 + c] = packh2(accO[nt][0] * inv0, accO[nt][1] * inv0);
        *(uint32_t*)&out[r1 + c] = packh2(accO[nt][2] * inv1, accO[nt][3] * inv1);
    }
}

// ---------------------------------------------------------------------------
extern "C" void kernel_launch(void* const* d_in, const int* in_sizes, int n_in,
                              void* d_out, int out_size)
{
    const float* x     = (const float*)d_in[0];
    const float* w_qkv = (const float*)d_in[1];
    const float* b_qkv = (const float*)d_in[2];
    const float* w_out = (const float*)d_in[3];
    const float* b_out = (const float*)d_in[4];
    float* out = (float*)d_out;

    __half* xh;    cudaGetSymbolAddress((void**)&xh,   g_xh);
    __half* wqt;   cudaGetSymbolAddress((void**)&wqt,  g_wqt);
    __half* wot;   cudaGetSymbolAddress((void**)&wot,  g_wot);
    __half* qkvh;  cudaGetSymbolAddress((void**)&qkvh, g_qkvh);
    __half* atth;  cudaGetSymbolAddress((void**)&atth, g_atth);

    // 0) prep: convert x, transpose-convert weights to fp16
    {
        int n4 = MROWS * DMODEL / 4;
        cvt_f32_to_f16<<<(n4 + 255) / 256, 256>>>(x, xh, n4);
        dim3 blk(32, 8);
        transpose_cvt<<<dim3(QKVCOLS / 32, DMODEL / 32), blk>>>(w_qkv, wqt,
                                                                DMODEL, QKVCOLS);
        transpose_cvt<<<dim3(DMODEL / 32, DMODEL / 32), blk>>>(w_out, wot,
                                                               DMODEL, DMODEL);
    }

    const int gemm_smem = NSTAGE * STG_HALVES * 2;     // 81920 B
    cudaFuncSetAttribute(gemm_f16<true>,
                         cudaFuncAttributeMaxDynamicSharedMemorySize, gemm_smem);
    cudaFuncSetAttribute(gemm_f16<false>,
                         cudaFuncAttributeMaxDynamicSharedMemorySize, gemm_smem);

    // 1) QKV projection (fp16, cp.async + ldmatrix)
    {
        dim3 grid(QKVCOLS / 128, MROWS / 128);   // (24, 64)
        gemm_f16<true><<<grid, 256, gemm_smem>>>(xh, wqt, b_qkv, qkvh,
                                                 MROWS, QKVCOLS, DMODEL);
    }

    // 2) causal flash attention (fp16 + ldmatrix)
    {
        const int smem = (QT * HQS + 2 * KT * HQS + QT * HQS) * 2; // 55296 B
        cudaFuncSetAttribute(attn_f16,
                             cudaFuncAttributeMaxDynamicSharedMemorySize, smem);
        dim3 grid(BB * NH, NTOK / QT);    // (64, 16)
        attn_f16<<<grid, 256, smem>>>(qkvh, atth);
    }

    // 3) output projection (fp16 in, fp32 out)
    {
        dim3 grid(DMODEL / 128, MROWS / 128);    // (8, 64)
        gemm_f16<false><<<grid, 256, gemm_smem>>>(atth, wot, b_out, out,
                                                  MROWS, DMODEL, DMODEL);
    }
}